// round 13
// baseline (speedup 1.0000x reference)
#include <cuda_runtime.h>
#include <cuda_bf16.h>

// ---------------------------------------------------------------------------
// EngramModule fused forward.
// Stage 1a: V table (16384x128 fp32) via FFMA2 GEMM, 64x64 tiles (512 blocks).
// Stage 1b: K table (16384x512 bf16) via warp-level bf16 MMA (HMMA).
// Stage 2:  main fused kernel (R10 structure), 6 blocks/SM.
// ---------------------------------------------------------------------------

#define Bq    8
#define Tq    4096
#define CHq   512
#define R_TOK 16
#define CHUNKS (Tq / R_TOK)   // 256

__device__ float         g_Vtab[16384 * 128];   // 8 MB fp32
__device__ __nv_bfloat16 g_Ktab[16384 * 512];   // 16 MB bf16

__device__ __forceinline__ unsigned long long pk2(float lo, float hi) {
    unsigned long long r;
    asm("mov.b64 %0, {%1, %2};" : "=l"(r) : "f"(lo), "f"(hi));
    return r;
}
__device__ __forceinline__ void upk2(float& lo, float& hi, unsigned long long v) {
    asm("mov.b64 {%0, %1}, %2;" : "=f"(lo), "=f"(hi) : "l"(v));
}
__device__ __forceinline__ void ffma2(unsigned long long& d,
                                      unsigned long long a,
                                      unsigned long long b) {
    asm("fma.rn.f32x2 %0, %1, %2, %0;" : "+l"(d) : "l"(a), "l"(b));
}

// ---------------------------------------------------------------------------
// Stage 1a: V table, fp32 FFMA2 GEMM.
// Block = 64 rows x 64 cols, 128 threads, 4x8 microtile, k-chunks of 16.
// Grid (2, 64, 4) = 512 blocks.
// ---------------------------------------------------------------------------
__global__ void __launch_bounds__(128) precompute_v_kernel(
    const float* __restrict__ emb,      // (16384, 64)
    const float* __restrict__ valW,     // (128, 256)
    const float* __restrict__ valb)     // (128)
{
    __shared__ __align__(16) float As[16][68];
    __shared__ __align__(16) float Bs[16][68];

    const int tid  = threadIdx.x;
    const int nblk = blockIdx.x;   // 0..1  (64-col tile within V)
    const int mblk = blockIdx.y;   // 0..63 (64-row tile within group)
    const int g    = blockIdx.z;   // 0..3

    const int row0 = (tid >> 3) << 2;   // 0..60  (4-row micro)
    const int col0 = (tid & 7) << 3;    // 0..56  (8-col micro)

    unsigned long long acc2[4][4];
#pragma unroll
    for (int i = 0; i < 4; i++)
#pragma unroll
        for (int j = 0; j < 4; j++) acc2[i][j] = 0ull;

    const int gcol0 = nblk << 6;
    const float* abase = emb + (size_t)((g << 12) + (mblk << 6)) * 64;
    const float* bbase = valW + (size_t)gcol0 * 256 + g * 64;

#pragma unroll
    for (int kc = 0; kc < 4; kc++) {
        // A: 64 rows x 16 e -> 2 float4/thread (coalesced)
#pragma unroll
        for (int u = 0; u < 2; u++) {
            const int f   = tid + (u << 7);     // 0..255
            const int row = f >> 2;             // 0..63
            const int j   = (f & 3) << 2;       // e-offset
            float4 av = *(const float4*)(abase + row * 64 + kc * 16 + j);
            As[j + 0][row] = av.x; As[j + 1][row] = av.y;
            As[j + 2][row] = av.z; As[j + 3][row] = av.w;
        }
        // B: 64 cols x 16 e -> 2 float4/thread (coalesced)
#pragma unroll
        for (int u = 0; u < 2; u++) {
            const int f   = tid + (u << 7);
            const int row = f >> 2;             // 0..63 (col index)
            const int j   = (f & 3) << 2;
            float4 bv = *(const float4*)(bbase + row * 256 + kc * 16 + j);
            Bs[j + 0][row] = bv.x; Bs[j + 1][row] = bv.y;
            Bs[j + 2][row] = bv.z; Bs[j + 3][row] = bv.w;
        }
        __syncthreads();
#pragma unroll
        for (int e = 0; e < 16; e++) {
            float4 a  = *(const float4*)&As[e][row0];
            float4 b0 = *(const float4*)&Bs[e][col0];
            float4 b1 = *(const float4*)&Bs[e][col0 + 4];
            unsigned long long bj[4] = {pk2(b0.x, b0.y), pk2(b0.z, b0.w),
                                        pk2(b1.x, b1.y), pk2(b1.z, b1.w)};
            float ar[4] = {a.x, a.y, a.z, a.w};
#pragma unroll
            for (int i = 0; i < 4; i++) {
                unsigned long long ai = pk2(ar[i], ar[i]);
#pragma unroll
                for (int j = 0; j < 4; j++)
                    ffma2(acc2[i][j], ai, bj[j]);
            }
        }
        __syncthreads();
    }

    const int slot0 = (g << 12) + (mblk << 6) + row0;
    const int gcol  = gcol0 + col0;
    float4 bia = *(const float4*)(valb + gcol);
    float4 bib = *(const float4*)(valb + gcol + 4);

#pragma unroll
    for (int i = 0; i < 4; i++) {
        float r[8];
        upk2(r[0], r[1], acc2[i][0]);
        upk2(r[2], r[3], acc2[i][1]);
        upk2(r[4], r[5], acc2[i][2]);
        upk2(r[6], r[7], acc2[i][3]);
        float* dst = g_Vtab + (size_t)(slot0 + i) * 128 + gcol;
        *(float4*)(dst)     = make_float4(r[0] + 0.25f * bia.x,
                                          r[1] + 0.25f * bia.y,
                                          r[2] + 0.25f * bia.z,
                                          r[3] + 0.25f * bia.w);
        *(float4*)(dst + 4) = make_float4(r[4] + 0.25f * bib.x,
                                          r[5] + 0.25f * bib.y,
                                          r[6] + 0.25f * bib.z,
                                          r[7] + 0.25f * bib.w);
    }
}

// ---------------------------------------------------------------------------
// Stage 1b: K table via bf16 warp-MMA (unchanged R11, measured ~11.7us).
// ---------------------------------------------------------------------------
__global__ void __launch_bounds__(256) ktab_mma_kernel(
    const float* __restrict__ emb,      // (16384, 64)
    const float* __restrict__ keyW,     // (512, 256)
    const float* __restrict__ keyb)     // (512)
{
    __shared__ __align__(16) __nv_bfloat16 Asm[128 * 72];
    __shared__ __align__(16) __nv_bfloat16 Bsm[64 * 72];

    const int tid  = threadIdx.x;
    const int nblk = blockIdx.x;   // 0..7
    const int mblk = blockIdx.y;   // 0..31
    const int g    = blockIdx.z;   // 0..3

    const float* abase = emb + (size_t)((g << 12) + (mblk << 7)) * 64;
#pragma unroll
    for (int u = 0; u < 8; u++) {
        const int idx = tid + (u << 8);
        const int row = idx >> 4;
        const int c4  = idx & 15;
        float4 v = *(const float4*)(abase + row * 64 + c4 * 4);
        __nv_bfloat162 p0 = __float22bfloat162_rn(make_float2(v.x, v.y));
        __nv_bfloat162 p1 = __float22bfloat162_rn(make_float2(v.z, v.w));
        uint2 w;
        w.x = *(unsigned int*)&p0;  w.y = *(unsigned int*)&p1;
        *(uint2*)(Asm + row * 72 + c4 * 4) = w;
    }
    const float* bbase = keyW + (size_t)(nblk << 6) * 256 + g * 64;
#pragma unroll
    for (int u = 0; u < 4; u++) {
        const int idx = tid + (u << 8);
        const int row = idx >> 4;
        const int c4  = idx & 15;
        float4 v = *(const float4*)(bbase + row * 256 + c4 * 4);
        __nv_bfloat162 p0 = __float22bfloat162_rn(make_float2(v.x, v.y));
        __nv_bfloat162 p1 = __float22bfloat162_rn(make_float2(v.z, v.w));
        uint2 w;
        w.x = *(unsigned int*)&p0;  w.y = *(unsigned int*)&p1;
        *(uint2*)(Bsm + row * 72 + c4 * 4) = w;
    }
    __syncthreads();

    const int warp = tid >> 5;
    const int lane = tid & 31;
    const int wm = warp & 3;
    const int wn = warp >> 2;

    float acc[2][4][4];
#pragma unroll
    for (int mi = 0; mi < 2; mi++)
#pragma unroll
        for (int ni = 0; ni < 4; ni++)
#pragma unroll
            for (int r = 0; r < 4; r++) acc[mi][ni][r] = 0.f;

    const unsigned int asmb = (unsigned int)__cvta_generic_to_shared(Asm);
    const unsigned int bsmb = (unsigned int)__cvta_generic_to_shared(Bsm);
    const int arow  = lane & 15;
    const int ahalf = lane >> 4;
    const int brow  = lane & 7;
    const int bhalf = (lane >> 3) & 1;

#pragma unroll
    for (int ks = 0; ks < 4; ks++) {
        unsigned int af[2][4];
#pragma unroll
        for (int mi = 0; mi < 2; mi++) {
            unsigned int addr = asmb
                + (unsigned int)((wm * 32 + mi * 16 + arow) * 144)
                + ks * 32 + ahalf * 16;
            asm volatile(
                "ldmatrix.sync.aligned.m8n8.x4.shared.b16 {%0,%1,%2,%3}, [%4];"
                : "=r"(af[mi][0]), "=r"(af[mi][1]),
                  "=r"(af[mi][2]), "=r"(af[mi][3])
                : "r"(addr));
        }
#pragma unroll
        for (int ni = 0; ni < 4; ni++) {
            unsigned int bf0, bf1;
            unsigned int baddr = bsmb
                + (unsigned int)((wn * 32 + ni * 8 + brow) * 144)
                + ks * 32 + bhalf * 16;
            asm volatile(
                "ldmatrix.sync.aligned.m8n8.x2.shared.b16 {%0,%1}, [%2];"
                : "=r"(bf0), "=r"(bf1) : "r"(baddr));
#pragma unroll
            for (int mi = 0; mi < 2; mi++) {
                asm volatile(
                    "mma.sync.aligned.m16n8k16.row.col.f32.bf16.bf16.f32 "
                    "{%0,%1,%2,%3}, {%4,%5,%6,%7}, {%8,%9}, {%0,%1,%2,%3};"
                    : "+f"(acc[mi][ni][0]), "+f"(acc[mi][ni][1]),
                      "+f"(acc[mi][ni][2]), "+f"(acc[mi][ni][3])
                    : "r"(af[mi][0]), "r"(af[mi][1]),
                      "r"(af[mi][2]), "r"(af[mi][3]),
                      "r"(bf0), "r"(bf1));
            }
        }
    }

    const int slotBase = (g << 12) + (mblk << 7) + wm * 32 + (lane >> 2);
    const int colBase  = (nblk << 6) + wn * 32 + (lane & 3) * 2;
#pragma unroll
    for (int ni = 0; ni < 4; ni++) {
        const int col = colBase + ni * 8;
        const float b0 = 0.25f * __ldg(keyb + col);
        const float b1 = 0.25f * __ldg(keyb + col + 1);
#pragma unroll
        for (int mi = 0; mi < 2; mi++) {
            __nv_bfloat162 lo = __float22bfloat162_rn(
                make_float2(acc[mi][ni][0] + b0, acc[mi][ni][1] + b1));
            __nv_bfloat162 hi = __float22bfloat162_rn(
                make_float2(acc[mi][ni][2] + b0, acc[mi][ni][3] + b1));
            *(unsigned int*)(g_Ktab + (size_t)(slotBase + mi * 16) * 512 + col)
                = *(unsigned int*)&lo;
            *(unsigned int*)(g_Ktab + (size_t)(slotBase + mi * 16 + 8) * 512 + col)
                = *(unsigned int*)&hi;
        }
    }
}

// ---------------------------------------------------------------------------
// Stage 2 main kernel (R10 structure), 6 blocks/SM target.
// ---------------------------------------------------------------------------
struct Tok {
    uint2  K0, K1, K2, K3;
    float4 v0, v1, v2, v3;
    float4 q;
};

__device__ __forceinline__ float4 bf4(uint2 u) {
    float2 a = __bfloat1622float2(*reinterpret_cast<const __nv_bfloat162*>(&u.x));
    float2 b = __bfloat1622float2(*reinterpret_cast<const __nv_bfloat162*>(&u.y));
    return make_float4(a.x, a.y, b.x, b.y);
}

__global__ void __launch_bounds__(128, 6) engram_main_kernel(
    const float* __restrict__ x,        // (B,T,4,128)
    const int*   __restrict__ ids,      // (B,T)
    const int*   __restrict__ mult,     // (2,2,3)
    const float* __restrict__ wq,       // (4,128)
    const float* __restrict__ wk,       // (4,128)
    const float* __restrict__ convw,    // (512,4)
    const float* __restrict__ convn,    // (4,128)
    float*       __restrict__ out)      // (B,T,4,128)
{
    const int stream = threadIdx.x >> 5;
    const int lane   = threadIdx.x & 31;
    const int b      = blockIdx.x >> 8;
    const int chunk  = blockIdx.x & 255;
    const int t0     = chunk * R_TOK;

    const int c = stream * 128 + lane * 4;
    const int d = lane * 4;

    const float4 wq4  = *(const float4*)(wq + c);
    const float4 wk4  = *(const float4*)(wk + c);
    const float4 wqk4 = make_float4(wq4.x * wk4.x, wq4.y * wk4.y,
                                    wq4.z * wk4.z, wq4.w * wk4.w);
    const float4 cvn4 = *(const float4*)(convn + c);
    const float4 cwA  = *(const float4*)(convw + (c + 0) * 4);
    const float4 cwB  = *(const float4*)(convw + (c + 1) * 4);
    const float4 cwC  = *(const float4*)(convw + (c + 2) * 4);
    const float4 cwD  = *(const float4*)(convw + (c + 3) * 4);

    const int m00 = mult[0],  m01 = mult[1];
    const int m10 = mult[3],  m11 = mult[4];
    const int m20 = mult[6],  m21 = mult[7],  m22 = mult[8];
    const int m30 = mult[9],  m31 = mult[10], m32 = mult[11];

    const float inv128     = 0.0078125f;
    const float eps        = 1.1920929e-7f;
    const float invsqrt128 = 0.08838834764831845f;

    const int    idBase = b * Tq;
    const float* xBase  = x   + (size_t)idBase * CHq + c;
    float*       oBase  = out + (size_t)idBase * CHq + c;

    float4 h1 = make_float4(0.f, 0.f, 0.f, 0.f);
    float4 h2 = h1;
    float4 h3 = h1;

    auto gather = [&](Tok& T, int ia, int ib, int ic, int t) {
        const int h0i = (((ib * m00) ^ (ic * m01)) & 4095);
        const int h1i = (((ib * m10) ^ (ic * m11)) & 4095) + 4096;
        const int h2i = (((ia * m20) ^ (ib * m21) ^ (ic * m22)) & 4095) + 8192;
        const int h3i = (((ia * m30) ^ (ib * m31) ^ (ic * m32)) & 4095) + 12288;
        T.K0 = __ldg((const uint2*)(g_Ktab + (size_t)h0i * 512 + c));
        T.K1 = __ldg((const uint2*)(g_Ktab + (size_t)h1i * 512 + c));
        T.K2 = __ldg((const uint2*)(g_Ktab + (size_t)h2i * 512 + c));
        T.K3 = __ldg((const uint2*)(g_Ktab + (size_t)h3i * 512 + c));
        T.v0 = __ldg((const float4*)(g_Vtab + (size_t)h0i * 128 + d));
        T.v1 = __ldg((const float4*)(g_Vtab + (size_t)h1i * 128 + d));
        T.v2 = __ldg((const float4*)(g_Vtab + (size_t)h2i * 128 + d));
        T.v3 = __ldg((const float4*)(g_Vtab + (size_t)h3i * 128 + d));
        T.q  = *(const float4*)(xBase + (size_t)t * CHq);
    };

    auto compute = [&](const Tok& T, int t, bool store) {
        const float4 k0 = bf4(T.K0);
        const float4 k1 = bf4(T.K1);
        const float4 k2 = bf4(T.K2);
        const float4 k3 = bf4(T.K3);
        float4 kr, vb;
        kr.x = (k0.x + k1.x) + (k2.x + k3.x);
        kr.y = (k0.y + k1.y) + (k2.y + k3.y);
        kr.z = (k0.z + k1.z) + (k2.z + k3.z);
        kr.w = (k0.w + k1.w) + (k2.w + k3.w);
        vb.x = (T.v0.x + T.v1.x) + (T.v2.x + T.v3.x);
        vb.y = (T.v0.y + T.v1.y) + (T.v2.y + T.v3.y);
        vb.z = (T.v0.z + T.v1.z) + (T.v2.z + T.v3.z);
        vb.w = (T.v0.w + T.v1.w) + (T.v2.w + T.v3.w);

        float p0 = T.q.x * T.q.x + T.q.y * T.q.y + T.q.z * T.q.z + T.q.w * T.q.w;
        float p1 = kr.x * kr.x + kr.y * kr.y + kr.z * kr.z + kr.w * kr.w;
        float p2 = T.q.x * kr.x * wqk4.x + T.q.y * kr.y * wqk4.y
                 + T.q.z * kr.z * wqk4.z + T.q.w * kr.w * wqk4.w;
        float p3 = vb.x * vb.x + vb.y * vb.y + vb.z * vb.z + vb.w * vb.w;

        const bool lo = (lane < 16);
        float ea = __shfl_xor_sync(0xffffffffu, p0, 16);
        float eb = __shfl_xor_sync(0xffffffffu, p2, 16);
        float aa = lo ? (p0 + ea) : (p2 + eb);
        float ec = __shfl_xor_sync(0xffffffffu, p1, 16);
        float ed = __shfl_xor_sync(0xffffffffu, p3, 16);
        float bb = lo ? (p1 + ec) : (p3 + ed);
#pragma unroll
        for (int off = 8; off; off >>= 1) {
            aa += __shfl_xor_sync(0xffffffffu, aa, off);
            bb += __shfl_xor_sync(0xffffffffu, bb, off);
        }
        const float a2 = __shfl_xor_sync(0xffffffffu, aa, 16);
        const float b2 = __shfl_xor_sync(0xffffffffu, bb, 16);
        const float sq  = lo ? aa : a2;
        const float sk  = lo ? bb : b2;
        const float sqk = lo ? a2 : aa;
        const float svb = lo ? b2 : bb;

        const float rsq   = rsqrtf(sq * inv128 + eps);
        const float rsk   = rsqrtf(sk * inv128 + eps);
        const float score = sqk * rsq * rsk * invsqrt128;
        const float gate  = __fdividef(1.f, 1.f + __expf(-score));
        const float rr    = rsqrtf(gate * gate * svb * inv128 + eps) * gate;

        float4 xn;
        xn.x = vb.x * rr * cvn4.x;  xn.y = vb.y * rr * cvn4.y;
        xn.z = vb.z * rr * cvn4.z;  xn.w = vb.w * rr * cvn4.w;

        if (store) {
            float4 y;
            y.x = cwA.x * h3.x + cwA.y * h2.x + cwA.z * h1.x + cwA.w * xn.x;
            y.y = cwB.x * h3.y + cwB.y * h2.y + cwB.z * h1.y + cwB.w * xn.y;
            y.z = cwC.x * h3.z + cwC.y * h2.z + cwC.z * h1.z + cwC.w * xn.z;
            y.w = cwD.x * h3.w + cwD.y * h2.w + cwD.z * h1.w + cwD.w * xn.w;
            y.x = __fdividef(y.x, 1.f + __expf(-y.x));
            y.y = __fdividef(y.y, 1.f + __expf(-y.y));
            y.z = __fdividef(y.z, 1.f + __expf(-y.z));
            y.w = __fdividef(y.w, 1.f + __expf(-y.w));
            float4 o;
            o.x = vb.x * gate + y.x;  o.y = vb.y * gate + y.y;
            o.z = vb.z * gate + y.z;  o.w = vb.w * gate + y.w;
            *(float4*)(oBase + (size_t)t * CHq) = o;
        }
        h3 = h2; h2 = h1; h1 = xn;
    };

    int ia = (t0 - 5 >= 0) ? __ldg(ids + idBase + t0 - 5) : 0;
    int ib = (t0 - 4 >= 0) ? __ldg(ids + idBase + t0 - 4) : 0;

#pragma unroll
    for (int tt = -3; tt < 0; tt++) {
        const int t  = t0 + tt;
        const int ic = (t >= 0) ? __ldg(ids + idBase + t) : 0;
        if (t >= 0) {
            Tok P;
            gather(P, ia, ib, ic, t);
            compute(P, t, false);
        }
        ia = ib; ib = ic;
    }

    int ic = __ldg(ids + idBase + t0);
    Tok cur;
    gather(cur, ia, ib, ic, t0);

    for (int tt = 0; tt < R_TOK; tt++) {
        const int t = t0 + tt;
        Tok nxt;
        int in_ = ic;
        if (tt + 1 < R_TOK) {
            in_ = __ldg(ids + idBase + t + 1);
            gather(nxt, ib, ic, in_, t + 1);
        }
        compute(cur, t, true);
        ia = ib; ib = ic; ic = in_;
        cur = nxt;
    }
}

// ---------------------------------------------------------------------------
extern "C" void kernel_launch(void* const* d_in, const int* in_sizes, int n_in,
                              void* d_out, int out_size)
{
    const float* x          = (const float*)d_in[0];
    const int*   input_ids  = (const int*)  d_in[1];
    const int*   multipliers= (const int*)  d_in[2];
    const float* embedding  = (const float*)d_in[3];
    const float* val_W      = (const float*)d_in[4];
    const float* val_b      = (const float*)d_in[5];
    const float* key_W      = (const float*)d_in[6];
    const float* key_b      = (const float*)d_in[7];
    const float* normq_w    = (const float*)d_in[8];
    const float* normk_w    = (const float*)d_in[9];
    const float* conv_w     = (const float*)d_in[10];
    const float* convnorm_w = (const float*)d_in[11];
    float* out = (float*)d_out;

    precompute_v_kernel<<<dim3(2, 64, 4), 128>>>(embedding, val_W, val_b);
    ktab_mma_kernel<<<dim3(8, 32, 4), 256>>>(embedding, key_W, key_b);

    engram_main_kernel<<<Bq * CHUNKS, 128>>>(
        x, input_ids, multipliers,
        normq_w, normk_w, conv_w, convnorm_w, out);
}

// round 14
// speedup vs baseline: 1.2437x; 1.2437x over previous
#include <cuda_runtime.h>
#include <cuda_bf16.h>

// ---------------------------------------------------------------------------
// EngramModule fused forward.
// Stage 1a: V table (16384x128 fp32) via SPLIT-PRECISION bf16 HMMA:
//           emb = hi+lo, valW = Whi+Wlo;  V ~= hi*Whi + hi*Wlo + lo*Whi
//           (error ~2^-17, fp32 accumulate, fp32 storage).
// Stage 1b: K table (16384x512 bf16) via bf16 HMMA (proven R11).
// Stage 2:  main fused kernel (proven R11, (128,5)).
// ---------------------------------------------------------------------------

#define Bq    8
#define Tq    4096
#define CHq   512
#define R_TOK 16
#define CHUNKS (Tq / R_TOK)   // 256

__device__ float         g_Vtab[16384 * 128];   // 8 MB fp32
__device__ __nv_bfloat16 g_Ktab[16384 * 512];   // 16 MB bf16

// ---------------------------------------------------------------------------
// Stage 1a: V table via split-bf16 MMA.
// Block = 256 thr = 8 warps; tile 64 slots x 64 V-cols, K=64 (4 k16-steps).
// Warp (wm 0..3, wn 0..1) computes 16 rows x 32 cols = 1m x 4n tiles.
// Smem rows padded to 72 bf16 (144 B) -> ldmatrix conflict-free.
// ---------------------------------------------------------------------------
__global__ void __launch_bounds__(256) vtab_mma_kernel(
    const float* __restrict__ emb,      // (16384, 64)
    const float* __restrict__ valW,     // (128, 256)
    const float* __restrict__ valb)     // (128)
{
    __shared__ __align__(16) __nv_bfloat16 Ahi[64 * 72];
    __shared__ __align__(16) __nv_bfloat16 Alo[64 * 72];
    __shared__ __align__(16) __nv_bfloat16 Bhi[64 * 72];
    __shared__ __align__(16) __nv_bfloat16 Blo[64 * 72];

    const int tid  = threadIdx.x;
    const int nblk = blockIdx.x;   // 0..1  -> V cols [nblk*64, +64)
    const int mblk = blockIdx.y;   // 0..63 -> 64-slot tile
    const int g    = blockIdx.z;   // 0..3

    // ---- stage A (emb tile 64x64) and B (valW tile 64x64), hi/lo split ----
    const float* abase = emb  + (size_t)((g << 12) + (mblk << 6)) * 64;
    const float* bbase = valW + (size_t)(nblk << 6) * 256 + g * 64;
#pragma unroll
    for (int u = 0; u < 4; u++) {
        const int idx = tid + (u << 8);     // 0..1023
        const int row = idx >> 4;           // 0..63
        const int c4  = idx & 15;

        float4 va = *(const float4*)(abase + row * 64 + c4 * 4);
        float4 vb = *(const float4*)(bbase + row * 256 + c4 * 4);

        // hi = bf16(v), lo = bf16(v - hi)
        __nv_bfloat162 ah0 = __float22bfloat162_rn(make_float2(va.x, va.y));
        __nv_bfloat162 ah1 = __float22bfloat162_rn(make_float2(va.z, va.w));
        __nv_bfloat162 al0 = __float22bfloat162_rn(make_float2(
            va.x - __bfloat162float(__low2bfloat16(ah0)),
            va.y - __bfloat162float(__high2bfloat16(ah0))));
        __nv_bfloat162 al1 = __float22bfloat162_rn(make_float2(
            va.z - __bfloat162float(__low2bfloat16(ah1)),
            va.w - __bfloat162float(__high2bfloat16(ah1))));
        __nv_bfloat162 bh0 = __float22bfloat162_rn(make_float2(vb.x, vb.y));
        __nv_bfloat162 bh1 = __float22bfloat162_rn(make_float2(vb.z, vb.w));
        __nv_bfloat162 bl0 = __float22bfloat162_rn(make_float2(
            vb.x - __bfloat162float(__low2bfloat16(bh0)),
            vb.y - __bfloat162float(__high2bfloat16(bh0))));
        __nv_bfloat162 bl1 = __float22bfloat162_rn(make_float2(
            vb.z - __bfloat162float(__low2bfloat16(bh1)),
            vb.w - __bfloat162float(__high2bfloat16(bh1))));

        uint2 w;
        w.x = *(unsigned int*)&ah0;  w.y = *(unsigned int*)&ah1;
        *(uint2*)(Ahi + row * 72 + c4 * 4) = w;
        w.x = *(unsigned int*)&al0;  w.y = *(unsigned int*)&al1;
        *(uint2*)(Alo + row * 72 + c4 * 4) = w;
        w.x = *(unsigned int*)&bh0;  w.y = *(unsigned int*)&bh1;
        *(uint2*)(Bhi + row * 72 + c4 * 4) = w;
        w.x = *(unsigned int*)&bl0;  w.y = *(unsigned int*)&bl1;
        *(uint2*)(Blo + row * 72 + c4 * 4) = w;
    }
    __syncthreads();

    const int warp = tid >> 5;
    const int lane = tid & 31;
    const int wm = warp & 3;        // 16-row strip
    const int wn = warp >> 2;       // 32-col strip

    float acc[4][4];
#pragma unroll
    for (int ni = 0; ni < 4; ni++)
#pragma unroll
        for (int r = 0; r < 4; r++) acc[ni][r] = 0.f;

    const unsigned int ahib = (unsigned int)__cvta_generic_to_shared(Ahi);
    const unsigned int alob = (unsigned int)__cvta_generic_to_shared(Alo);
    const unsigned int bhib = (unsigned int)__cvta_generic_to_shared(Bhi);
    const unsigned int blob = (unsigned int)__cvta_generic_to_shared(Blo);
    const int arow  = lane & 15;
    const int ahalf = lane >> 4;
    const int brow  = lane & 7;
    const int bhalf = (lane >> 3) & 1;

#pragma unroll
    for (int ks = 0; ks < 4; ks++) {
        const unsigned int aoff =
            (unsigned int)((wm * 16 + arow) * 144) + ks * 32 + ahalf * 16;
        unsigned int ah[4], al[4];
        asm volatile(
            "ldmatrix.sync.aligned.m8n8.x4.shared.b16 {%0,%1,%2,%3}, [%4];"
            : "=r"(ah[0]), "=r"(ah[1]), "=r"(ah[2]), "=r"(ah[3])
            : "r"(ahib + aoff));
        asm volatile(
            "ldmatrix.sync.aligned.m8n8.x4.shared.b16 {%0,%1,%2,%3}, [%4];"
            : "=r"(al[0]), "=r"(al[1]), "=r"(al[2]), "=r"(al[3])
            : "r"(alob + aoff));
#pragma unroll
        for (int ni = 0; ni < 4; ni++) {
            const unsigned int boff =
                (unsigned int)((wn * 32 + ni * 8 + brow) * 144)
                + ks * 32 + bhalf * 16;
            unsigned int bh0, bh1, bl0, bl1;
            asm volatile(
                "ldmatrix.sync.aligned.m8n8.x2.shared.b16 {%0,%1}, [%2];"
                : "=r"(bh0), "=r"(bh1) : "r"(bhib + boff));
            asm volatile(
                "ldmatrix.sync.aligned.m8n8.x2.shared.b16 {%0,%1}, [%2];"
                : "=r"(bl0), "=r"(bl1) : "r"(blob + boff));
            // hi*Whi
            asm volatile(
                "mma.sync.aligned.m16n8k16.row.col.f32.bf16.bf16.f32 "
                "{%0,%1,%2,%3}, {%4,%5,%6,%7}, {%8,%9}, {%0,%1,%2,%3};"
                : "+f"(acc[ni][0]), "+f"(acc[ni][1]),
                  "+f"(acc[ni][2]), "+f"(acc[ni][3])
                : "r"(ah[0]), "r"(ah[1]), "r"(ah[2]), "r"(ah[3]),
                  "r"(bh0), "r"(bh1));
            // hi*Wlo
            asm volatile(
                "mma.sync.aligned.m16n8k16.row.col.f32.bf16.bf16.f32 "
                "{%0,%1,%2,%3}, {%4,%5,%6,%7}, {%8,%9}, {%0,%1,%2,%3};"
                : "+f"(acc[ni][0]), "+f"(acc[ni][1]),
                  "+f"(acc[ni][2]), "+f"(acc[ni][3])
                : "r"(ah[0]), "r"(ah[1]), "r"(ah[2]), "r"(ah[3]),
                  "r"(bl0), "r"(bl1));
            // lo*Whi
            asm volatile(
                "mma.sync.aligned.m16n8k16.row.col.f32.bf16.bf16.f32 "
                "{%0,%1,%2,%3}, {%4,%5,%6,%7}, {%8,%9}, {%0,%1,%2,%3};"
                : "+f"(acc[ni][0]), "+f"(acc[ni][1]),
                  "+f"(acc[ni][2]), "+f"(acc[ni][3])
                : "r"(al[0]), "r"(al[1]), "r"(al[2]), "r"(al[3]),
                  "r"(bh0), "r"(bh1));
        }
    }

    // epilogue: C frag mapping (same as proven K kernel):
    // c0,c1 -> (row = lane>>2, col = (lane&3)*2 {,+1}); c2,c3 -> row+8.
    const int slotBase = (g << 12) + (mblk << 6) + wm * 16 + (lane >> 2);
    const int colBase  = (nblk << 6) + wn * 32 + (lane & 3) * 2;
#pragma unroll
    for (int ni = 0; ni < 4; ni++) {
        const int col = colBase + ni * 8;
        const float b0 = 0.25f * __ldg(valb + col);
        const float b1 = 0.25f * __ldg(valb + col + 1);
        *(float2*)(g_Vtab + (size_t)slotBase * 128 + col)
            = make_float2(acc[ni][0] + b0, acc[ni][1] + b1);
        *(float2*)(g_Vtab + (size_t)(slotBase + 8) * 128 + col)
            = make_float2(acc[ni][2] + b0, acc[ni][3] + b1);
    }
}

// ---------------------------------------------------------------------------
// Stage 1b: K table via bf16 warp-MMA (unchanged R11, measured ~11.7us).
// ---------------------------------------------------------------------------
__global__ void __launch_bounds__(256) ktab_mma_kernel(
    const float* __restrict__ emb,      // (16384, 64)
    const float* __restrict__ keyW,     // (512, 256)
    const float* __restrict__ keyb)     // (512)
{
    __shared__ __align__(16) __nv_bfloat16 Asm[128 * 72];
    __shared__ __align__(16) __nv_bfloat16 Bsm[64 * 72];

    const int tid  = threadIdx.x;
    const int nblk = blockIdx.x;   // 0..7
    const int mblk = blockIdx.y;   // 0..31
    const int g    = blockIdx.z;   // 0..3

    const float* abase = emb + (size_t)((g << 12) + (mblk << 7)) * 64;
#pragma unroll
    for (int u = 0; u < 8; u++) {
        const int idx = tid + (u << 8);
        const int row = idx >> 4;
        const int c4  = idx & 15;
        float4 v = *(const float4*)(abase + row * 64 + c4 * 4);
        __nv_bfloat162 p0 = __float22bfloat162_rn(make_float2(v.x, v.y));
        __nv_bfloat162 p1 = __float22bfloat162_rn(make_float2(v.z, v.w));
        uint2 w;
        w.x = *(unsigned int*)&p0;  w.y = *(unsigned int*)&p1;
        *(uint2*)(Asm + row * 72 + c4 * 4) = w;
    }
    const float* bbase = keyW + (size_t)(nblk << 6) * 256 + g * 64;
#pragma unroll
    for (int u = 0; u < 4; u++) {
        const int idx = tid + (u << 8);
        const int row = idx >> 4;
        const int c4  = idx & 15;
        float4 v = *(const float4*)(bbase + row * 256 + c4 * 4);
        __nv_bfloat162 p0 = __float22bfloat162_rn(make_float2(v.x, v.y));
        __nv_bfloat162 p1 = __float22bfloat162_rn(make_float2(v.z, v.w));
        uint2 w;
        w.x = *(unsigned int*)&p0;  w.y = *(unsigned int*)&p1;
        *(uint2*)(Bsm + row * 72 + c4 * 4) = w;
    }
    __syncthreads();

    const int warp = tid >> 5;
    const int lane = tid & 31;
    const int wm = warp & 3;
    const int wn = warp >> 2;

    float acc[2][4][4];
#pragma unroll
    for (int mi = 0; mi < 2; mi++)
#pragma unroll
        for (int ni = 0; ni < 4; ni++)
#pragma unroll
            for (int r = 0; r < 4; r++) acc[mi][ni][r] = 0.f;

    const unsigned int asmb = (unsigned int)__cvta_generic_to_shared(Asm);
    const unsigned int bsmb = (unsigned int)__cvta_generic_to_shared(Bsm);
    const int arow  = lane & 15;
    const int ahalf = lane >> 4;
    const int brow  = lane & 7;
    const int bhalf = (lane >> 3) & 1;

#pragma unroll
    for (int ks = 0; ks < 4; ks++) {
        unsigned int af[2][4];
#pragma unroll
        for (int mi = 0; mi < 2; mi++) {
            unsigned int addr = asmb
                + (unsigned int)((wm * 32 + mi * 16 + arow) * 144)
                + ks * 32 + ahalf * 16;
            asm volatile(
                "ldmatrix.sync.aligned.m8n8.x4.shared.b16 {%0,%1,%2,%3}, [%4];"
                : "=r"(af[mi][0]), "=r"(af[mi][1]),
                  "=r"(af[mi][2]), "=r"(af[mi][3])
                : "r"(addr));
        }
#pragma unroll
        for (int ni = 0; ni < 4; ni++) {
            unsigned int bf0, bf1;
            unsigned int baddr = bsmb
                + (unsigned int)((wn * 32 + ni * 8 + brow) * 144)
                + ks * 32 + bhalf * 16;
            asm volatile(
                "ldmatrix.sync.aligned.m8n8.x2.shared.b16 {%0,%1}, [%2];"
                : "=r"(bf0), "=r"(bf1) : "r"(baddr));
#pragma unroll
            for (int mi = 0; mi < 2; mi++) {
                asm volatile(
                    "mma.sync.aligned.m16n8k16.row.col.f32.bf16.bf16.f32 "
                    "{%0,%1,%2,%3}, {%4,%5,%6,%7}, {%8,%9}, {%0,%1,%2,%3};"
                    : "+f"(acc[mi][ni][0]), "+f"(acc[mi][ni][1]),
                      "+f"(acc[mi][ni][2]), "+f"(acc[mi][ni][3])
                    : "r"(af[mi][0]), "r"(af[mi][1]),
                      "r"(af[mi][2]), "r"(af[mi][3]),
                      "r"(bf0), "r"(bf1));
            }
        }
    }

    const int slotBase = (g << 12) + (mblk << 7) + wm * 32 + (lane >> 2);
    const int colBase  = (nblk << 6) + wn * 32 + (lane & 3) * 2;
#pragma unroll
    for (int ni = 0; ni < 4; ni++) {
        const int col = colBase + ni * 8;
        const float b0 = 0.25f * __ldg(keyb + col);
        const float b1 = 0.25f * __ldg(keyb + col + 1);
#pragma unroll
        for (int mi = 0; mi < 2; mi++) {
            __nv_bfloat162 lo = __float22bfloat162_rn(
                make_float2(acc[mi][ni][0] + b0, acc[mi][ni][1] + b1));
            __nv_bfloat162 hi = __float22bfloat162_rn(
                make_float2(acc[mi][ni][2] + b0, acc[mi][ni][3] + b1));
            *(unsigned int*)(g_Ktab + (size_t)(slotBase + mi * 16) * 512 + col)
                = *(unsigned int*)&lo;
            *(unsigned int*)(g_Ktab + (size_t)(slotBase + mi * 16 + 8) * 512 + col)
                = *(unsigned int*)&hi;
        }
    }
}

// ---------------------------------------------------------------------------
// Stage 2 main kernel (proven R11, (128,5)).
// ---------------------------------------------------------------------------
struct Tok {
    uint2  K0, K1, K2, K3;
    float4 v0, v1, v2, v3;
    float4 q;
};

__device__ __forceinline__ float4 bf4(uint2 u) {
    float2 a = __bfloat1622float2(*reinterpret_cast<const __nv_bfloat162*>(&u.x));
    float2 b = __bfloat1622float2(*reinterpret_cast<const __nv_bfloat162*>(&u.y));
    return make_float4(a.x, a.y, b.x, b.y);
}

__global__ void __launch_bounds__(128, 5) engram_main_kernel(
    const float* __restrict__ x,        // (B,T,4,128)
    const int*   __restrict__ ids,      // (B,T)
    const int*   __restrict__ mult,     // (2,2,3)
    const float* __restrict__ wq,       // (4,128)
    const float* __restrict__ wk,       // (4,128)
    const float* __restrict__ convw,    // (512,4)
    const float* __restrict__ convn,    // (4,128)
    float*       __restrict__ out)      // (B,T,4,128)
{
    const int stream = threadIdx.x >> 5;
    const int lane   = threadIdx.x & 31;
    const int b      = blockIdx.x >> 8;
    const int chunk  = blockIdx.x & 255;
    const int t0     = chunk * R_TOK;

    const int c = stream * 128 + lane * 4;
    const int d = lane * 4;

    const float4 wq4  = *(const float4*)(wq + c);
    const float4 wk4  = *(const float4*)(wk + c);
    const float4 wqk4 = make_float4(wq4.x * wk4.x, wq4.y * wk4.y,
                                    wq4.z * wk4.z, wq4.w * wk4.w);
    const float4 cvn4 = *(const float4*)(convn + c);
    const float4 cwA  = *(const float4*)(convw + (c + 0) * 4);
    const float4 cwB  = *(const float4*)(convw + (c + 1) * 4);
    const float4 cwC  = *(const float4*)(convw + (c + 2) * 4);
    const float4 cwD  = *(const float4*)(convw + (c + 3) * 4);

    const int m00 = mult[0],  m01 = mult[1];
    const int m10 = mult[3],  m11 = mult[4];
    const int m20 = mult[6],  m21 = mult[7],  m22 = mult[8];
    const int m30 = mult[9],  m31 = mult[10], m32 = mult[11];

    const float inv128     = 0.0078125f;
    const float eps        = 1.1920929e-7f;
    const float invsqrt128 = 0.08838834764831845f;

    const int    idBase = b * Tq;
    const float* xBase  = x   + (size_t)idBase * CHq + c;
    float*       oBase  = out + (size_t)idBase * CHq + c;

    float4 h1 = make_float4(0.f, 0.f, 0.f, 0.f);
    float4 h2 = h1;
    float4 h3 = h1;

    auto gather = [&](Tok& T, int ia, int ib, int ic, int t) {
        const int h0i = (((ib * m00) ^ (ic * m01)) & 4095);
        const int h1i = (((ib * m10) ^ (ic * m11)) & 4095) + 4096;
        const int h2i = (((ia * m20) ^ (ib * m21) ^ (ic * m22)) & 4095) + 8192;
        const int h3i = (((ia * m30) ^ (ib * m31) ^ (ic * m32)) & 4095) + 12288;
        T.K0 = __ldg((const uint2*)(g_Ktab + (size_t)h0i * 512 + c));
        T.K1 = __ldg((const uint2*)(g_Ktab + (size_t)h1i * 512 + c));
        T.K2 = __ldg((const uint2*)(g_Ktab + (size_t)h2i * 512 + c));
        T.K3 = __ldg((const uint2*)(g_Ktab + (size_t)h3i * 512 + c));
        T.v0 = __ldg((const float4*)(g_Vtab + (size_t)h0i * 128 + d));
        T.v1 = __ldg((const float4*)(g_Vtab + (size_t)h1i * 128 + d));
        T.v2 = __ldg((const float4*)(g_Vtab + (size_t)h2i * 128 + d));
        T.v3 = __ldg((const float4*)(g_Vtab + (size_t)h3i * 128 + d));
        T.q  = *(const float4*)(xBase + (size_t)t * CHq);
    };

    auto compute = [&](const Tok& T, int t, bool store) {
        const float4 k0 = bf4(T.K0);
        const float4 k1 = bf4(T.K1);
        const float4 k2 = bf4(T.K2);
        const float4 k3 = bf4(T.K3);
        float4 kr, vb;
        kr.x = (k0.x + k1.x) + (k2.x + k3.x);
        kr.y = (k0.y + k1.y) + (k2.y + k3.y);
        kr.z = (k0.z + k1.z) + (k2.z + k3.z);
        kr.w = (k0.w + k1.w) + (k2.w + k3.w);
        vb.x = (T.v0.x + T.v1.x) + (T.v2.x + T.v3.x);
        vb.y = (T.v0.y + T.v1.y) + (T.v2.y + T.v3.y);
        vb.z = (T.v0.z + T.v1.z) + (T.v2.z + T.v3.z);
        vb.w = (T.v0.w + T.v1.w) + (T.v2.w + T.v3.w);

        float p0 = T.q.x * T.q.x + T.q.y * T.q.y + T.q.z * T.q.z + T.q.w * T.q.w;
        float p1 = kr.x * kr.x + kr.y * kr.y + kr.z * kr.z + kr.w * kr.w;
        float p2 = T.q.x * kr.x * wqk4.x + T.q.y * kr.y * wqk4.y
                 + T.q.z * kr.z * wqk4.z + T.q.w * kr.w * wqk4.w;
        float p3 = vb.x * vb.x + vb.y * vb.y + vb.z * vb.z + vb.w * vb.w;

        const bool lo = (lane < 16);
        float ea = __shfl_xor_sync(0xffffffffu, p0, 16);
        float eb = __shfl_xor_sync(0xffffffffu, p2, 16);
        float aa = lo ? (p0 + ea) : (p2 + eb);
        float ec = __shfl_xor_sync(0xffffffffu, p1, 16);
        float ed = __shfl_xor_sync(0xffffffffu, p3, 16);
        float bb = lo ? (p1 + ec) : (p3 + ed);
#pragma unroll
        for (int off = 8; off; off >>= 1) {
            aa += __shfl_xor_sync(0xffffffffu, aa, off);
            bb += __shfl_xor_sync(0xffffffffu, bb, off);
        }
        const float a2 = __shfl_xor_sync(0xffffffffu, aa, 16);
        const float b2 = __shfl_xor_sync(0xffffffffu, bb, 16);
        const float sq  = lo ? aa : a2;
        const float sk  = lo ? bb : b2;
        const float sqk = lo ? a2 : aa;
        const float svb = lo ? b2 : bb;

        const float rsq   = rsqrtf(sq * inv128 + eps);
        const float rsk   = rsqrtf(sk * inv128 + eps);
        const float score = sqk * rsq * rsk * invsqrt128;
        const float gate  = __fdividef(1.f, 1.f + __expf(-score));
        const float rr    = rsqrtf(gate * gate * svb * inv128 + eps) * gate;

        float4 xn;
        xn.x = vb.x * rr * cvn4.x;  xn.y = vb.y * rr * cvn4.y;
        xn.z = vb.z * rr * cvn4.z;  xn.w = vb.w * rr * cvn4.w;

        if (store) {
            float4 y;
            y.x = cwA.x * h3.x + cwA.y * h2.x + cwA.z * h1.x + cwA.w * xn.x;
            y.y = cwB.x * h3.y + cwB.y * h2.y + cwB.z * h1.y + cwB.w * xn.y;
            y.z = cwC.x * h3.z + cwC.y * h2.z + cwC.z * h1.z + cwC.w * xn.z;
            y.w = cwD.x * h3.w + cwD.y * h2.w + cwD.z * h1.w + cwD.w * xn.w;
            y.x = __fdividef(y.x, 1.f + __expf(-y.x));
            y.y = __fdividef(y.y, 1.f + __expf(-y.y));
            y.z = __fdividef(y.z, 1.f + __expf(-y.z));
            y.w = __fdividef(y.w, 1.f + __expf(-y.w));
            float4 o;
            o.x = vb.x * gate + y.x;  o.y = vb.y * gate + y.y;
            o.z = vb.z * gate + y.z;  o.w = vb.w * gate + y.w;
            *(float4*)(oBase + (size_t)t * CHq) = o;
        }
        h3 = h2; h2 = h1; h1 = xn;
    };

    int ia = (t0 - 5 >= 0) ? __ldg(ids + idBase + t0 - 5) : 0;
    int ib = (t0 - 4 >= 0) ? __ldg(ids + idBase + t0 - 4) : 0;

#pragma unroll
    for (int tt = -3; tt < 0; tt++) {
        const int t  = t0 + tt;
        const int ic = (t >= 0) ? __ldg(ids + idBase + t) : 0;
        if (t >= 0) {
            Tok P;
            gather(P, ia, ib, ic, t);
            compute(P, t, false);
        }
        ia = ib; ib = ic;
    }

    int ic = __ldg(ids + idBase + t0);
    Tok cur;
    gather(cur, ia, ib, ic, t0);

    for (int tt = 0; tt < R_TOK; tt++) {
        const int t = t0 + tt;
        Tok nxt;
        int in_ = ic;
        if (tt + 1 < R_TOK) {
            in_ = __ldg(ids + idBase + t + 1);
            gather(nxt, ib, ic, in_, t + 1);
        }
        compute(cur, t, true);
        ia = ib; ib = ic; ic = in_;
        cur = nxt;
    }
}

// ---------------------------------------------------------------------------
extern "C" void kernel_launch(void* const* d_in, const int* in_sizes, int n_in,
                              void* d_out, int out_size)
{
    const float* x          = (const float*)d_in[0];
    const int*   input_ids  = (const int*)  d_in[1];
    const int*   multipliers= (const int*)  d_in[2];
    const float* embedding  = (const float*)d_in[3];
    const float* val_W      = (const float*)d_in[4];
    const float* val_b      = (const float*)d_in[5];
    const float* key_W      = (const float*)d_in[6];
    const float* key_b      = (const float*)d_in[7];
    const float* normq_w    = (const float*)d_in[8];
    const float* normk_w    = (const float*)d_in[9];
    const float* conv_w     = (const float*)d_in[10];
    const float* convnorm_w = (const float*)d_in[11];
    float* out = (float*)d_out;

    vtab_mma_kernel<<<dim3(2, 64, 4), 256>>>(embedding, val_W, val_b);
    ktab_mma_kernel<<<dim3(8, 32, 4), 256>>>(embedding, key_W, key_b);

    engram_main_kernel<<<Bq * CHUNKS, 128>>>(
        x, input_ids, multipliers,
        normq_w, normk_w, conv_w, convnorm_w, out);
}

// round 15
// speedup vs baseline: 1.2779x; 1.0275x over previous
#include <cuda_runtime.h>
#include <cuda_bf16.h>

// ---------------------------------------------------------------------------
// EngramModule fused forward.
// Stage 1 (single merged launch, 1536 blocks, 1:2 V:K interleave):
//   blockIdx.x % 3 == 0 -> V table tile (64x64, split-bf16 HMMA, ~fp32 exact)
//   else                -> K table tile (128x64, bf16 HMMA)
// Stage 2: main fused kernel (proven, ~57us).
// ---------------------------------------------------------------------------

#define Bq    8
#define Tq    4096
#define CHq   512
#define R_TOK 16
#define CHUNKS (Tq / R_TOK)   // 256

__device__ float         g_Vtab[16384 * 128];   // 8 MB fp32
__device__ __nv_bfloat16 g_Ktab[16384 * 512];   // 16 MB bf16

// ---------------------------------------------------------------------------
// Stage 1: merged precompute. 256 threads; smem union 36864 B.
// ---------------------------------------------------------------------------
__global__ void __launch_bounds__(256) precompute_kernel(
    const float* __restrict__ emb,      // (16384, 64)
    const float* __restrict__ valW,     // (128, 256)
    const float* __restrict__ valb,     // (128)
    const float* __restrict__ keyW,     // (512, 256)
    const float* __restrict__ keyb)     // (512)
{
    __shared__ __align__(16) char smem_raw[36864];

    const int tid  = threadIdx.x;
    const int bx   = blockIdx.x;
    const int warp = tid >> 5;
    const int lane = tid & 31;

    if (bx % 3 == 0) {
        // ============ V path: split-bf16 HMMA, 64 slots x 64 cols ============
        const int vIdx = bx / 3;            // 0..511
        const int nblk = vIdx & 1;          // 0..1
        const int mblk = (vIdx >> 1) & 63;  // 0..63
        const int g    = vIdx >> 7;         // 0..3

        __nv_bfloat16* Ahi = (__nv_bfloat16*)(smem_raw);
        __nv_bfloat16* Alo = (__nv_bfloat16*)(smem_raw + 9216);
        __nv_bfloat16* Bhi = (__nv_bfloat16*)(smem_raw + 18432);
        __nv_bfloat16* Blo = (__nv_bfloat16*)(smem_raw + 27648);

        const float* abase = emb  + (size_t)((g << 12) + (mblk << 6)) * 64;
        const float* bbase = valW + (size_t)(nblk << 6) * 256 + g * 64;
#pragma unroll
        for (int u = 0; u < 4; u++) {
            const int idx = tid + (u << 8);     // 0..1023
            const int row = idx >> 4;           // 0..63
            const int c4  = idx & 15;

            float4 va = *(const float4*)(abase + row * 64 + c4 * 4);
            float4 vb = *(const float4*)(bbase + row * 256 + c4 * 4);

            __nv_bfloat162 ah0 = __float22bfloat162_rn(make_float2(va.x, va.y));
            __nv_bfloat162 ah1 = __float22bfloat162_rn(make_float2(va.z, va.w));
            __nv_bfloat162 al0 = __float22bfloat162_rn(make_float2(
                va.x - __bfloat162float(__low2bfloat16(ah0)),
                va.y - __bfloat162float(__high2bfloat16(ah0))));
            __nv_bfloat162 al1 = __float22bfloat162_rn(make_float2(
                va.z - __bfloat162float(__low2bfloat16(ah1)),
                va.w - __bfloat162float(__high2bfloat16(ah1))));
            __nv_bfloat162 bh0 = __float22bfloat162_rn(make_float2(vb.x, vb.y));
            __nv_bfloat162 bh1 = __float22bfloat162_rn(make_float2(vb.z, vb.w));
            __nv_bfloat162 bl0 = __float22bfloat162_rn(make_float2(
                vb.x - __bfloat162float(__low2bfloat16(bh0)),
                vb.y - __bfloat162float(__high2bfloat16(bh0))));
            __nv_bfloat162 bl1 = __float22bfloat162_rn(make_float2(
                vb.z - __bfloat162float(__low2bfloat16(bh1)),
                vb.w - __bfloat162float(__high2bfloat16(bh1))));

            uint2 w;
            w.x = *(unsigned int*)&ah0;  w.y = *(unsigned int*)&ah1;
            *(uint2*)(Ahi + row * 72 + c4 * 4) = w;
            w.x = *(unsigned int*)&al0;  w.y = *(unsigned int*)&al1;
            *(uint2*)(Alo + row * 72 + c4 * 4) = w;
            w.x = *(unsigned int*)&bh0;  w.y = *(unsigned int*)&bh1;
            *(uint2*)(Bhi + row * 72 + c4 * 4) = w;
            w.x = *(unsigned int*)&bl0;  w.y = *(unsigned int*)&bl1;
            *(uint2*)(Blo + row * 72 + c4 * 4) = w;
        }
        __syncthreads();

        const int wm = warp & 3;
        const int wn = warp >> 2;

        float acc[4][4];
#pragma unroll
        for (int ni = 0; ni < 4; ni++)
#pragma unroll
            for (int r = 0; r < 4; r++) acc[ni][r] = 0.f;

        const unsigned int ahib = (unsigned int)__cvta_generic_to_shared(Ahi);
        const unsigned int alob = (unsigned int)__cvta_generic_to_shared(Alo);
        const unsigned int bhib = (unsigned int)__cvta_generic_to_shared(Bhi);
        const unsigned int blob = (unsigned int)__cvta_generic_to_shared(Blo);
        const int arow  = lane & 15;
        const int ahalf = lane >> 4;
        const int brow  = lane & 7;
        const int bhalf = (lane >> 3) & 1;

#pragma unroll
        for (int ks = 0; ks < 4; ks++) {
            const unsigned int aoff =
                (unsigned int)((wm * 16 + arow) * 144) + ks * 32 + ahalf * 16;
            unsigned int ah[4], al[4];
            asm volatile(
                "ldmatrix.sync.aligned.m8n8.x4.shared.b16 {%0,%1,%2,%3}, [%4];"
                : "=r"(ah[0]), "=r"(ah[1]), "=r"(ah[2]), "=r"(ah[3])
                : "r"(ahib + aoff));
            asm volatile(
                "ldmatrix.sync.aligned.m8n8.x4.shared.b16 {%0,%1,%2,%3}, [%4];"
                : "=r"(al[0]), "=r"(al[1]), "=r"(al[2]), "=r"(al[3])
                : "r"(alob + aoff));
#pragma unroll
            for (int ni = 0; ni < 4; ni++) {
                const unsigned int boff =
                    (unsigned int)((wn * 32 + ni * 8 + brow) * 144)
                    + ks * 32 + bhalf * 16;
                unsigned int bh0, bh1, bl0, bl1;
                asm volatile(
                    "ldmatrix.sync.aligned.m8n8.x2.shared.b16 {%0,%1}, [%2];"
                    : "=r"(bh0), "=r"(bh1) : "r"(bhib + boff));
                asm volatile(
                    "ldmatrix.sync.aligned.m8n8.x2.shared.b16 {%0,%1}, [%2];"
                    : "=r"(bl0), "=r"(bl1) : "r"(blob + boff));
                asm volatile(
                    "mma.sync.aligned.m16n8k16.row.col.f32.bf16.bf16.f32 "
                    "{%0,%1,%2,%3}, {%4,%5,%6,%7}, {%8,%9}, {%0,%1,%2,%3};"
                    : "+f"(acc[ni][0]), "+f"(acc[ni][1]),
                      "+f"(acc[ni][2]), "+f"(acc[ni][3])
                    : "r"(ah[0]), "r"(ah[1]), "r"(ah[2]), "r"(ah[3]),
                      "r"(bh0), "r"(bh1));
                asm volatile(
                    "mma.sync.aligned.m16n8k16.row.col.f32.bf16.bf16.f32 "
                    "{%0,%1,%2,%3}, {%4,%5,%6,%7}, {%8,%9}, {%0,%1,%2,%3};"
                    : "+f"(acc[ni][0]), "+f"(acc[ni][1]),
                      "+f"(acc[ni][2]), "+f"(acc[ni][3])
                    : "r"(ah[0]), "r"(ah[1]), "r"(ah[2]), "r"(ah[3]),
                      "r"(bl0), "r"(bl1));
                asm volatile(
                    "mma.sync.aligned.m16n8k16.row.col.f32.bf16.bf16.f32 "
                    "{%0,%1,%2,%3}, {%4,%5,%6,%7}, {%8,%9}, {%0,%1,%2,%3};"
                    : "+f"(acc[ni][0]), "+f"(acc[ni][1]),
                      "+f"(acc[ni][2]), "+f"(acc[ni][3])
                    : "r"(al[0]), "r"(al[1]), "r"(al[2]), "r"(al[3]),
                      "r"(bh0), "r"(bh1));
            }
        }

        const int slotBase = (g << 12) + (mblk << 6) + wm * 16 + (lane >> 2);
        const int colBase  = (nblk << 6) + wn * 32 + (lane & 3) * 2;
#pragma unroll
        for (int ni = 0; ni < 4; ni++) {
            const int col = colBase + ni * 8;
            const float b0 = 0.25f * __ldg(valb + col);
            const float b1 = 0.25f * __ldg(valb + col + 1);
            *(float2*)(g_Vtab + (size_t)slotBase * 128 + col)
                = make_float2(acc[ni][0] + b0, acc[ni][1] + b1);
            *(float2*)(g_Vtab + (size_t)(slotBase + 8) * 128 + col)
                = make_float2(acc[ni][2] + b0, acc[ni][3] + b1);
        }
    } else {
        // ============ K path: bf16 HMMA, 128 slots x 64 cols ============
        const int kIdx = (bx / 3) * 2 + (bx % 3) - 1;   // 0..1023
        const int nblk = kIdx & 7;          // 0..7
        const int mblk = (kIdx >> 3) & 31;  // 0..31
        const int g    = kIdx >> 8;         // 0..3

        __nv_bfloat16* Asm = (__nv_bfloat16*)(smem_raw);
        __nv_bfloat16* Bsm = (__nv_bfloat16*)(smem_raw + 18432);

        const float* abase = emb + (size_t)((g << 12) + (mblk << 7)) * 64;
#pragma unroll
        for (int u = 0; u < 8; u++) {
            const int idx = tid + (u << 8);
            const int row = idx >> 4;
            const int c4  = idx & 15;
            float4 v = *(const float4*)(abase + row * 64 + c4 * 4);
            __nv_bfloat162 p0 = __float22bfloat162_rn(make_float2(v.x, v.y));
            __nv_bfloat162 p1 = __float22bfloat162_rn(make_float2(v.z, v.w));
            uint2 w;
            w.x = *(unsigned int*)&p0;  w.y = *(unsigned int*)&p1;
            *(uint2*)(Asm + row * 72 + c4 * 4) = w;
        }
        const float* bbase = keyW + (size_t)(nblk << 6) * 256 + g * 64;
#pragma unroll
        for (int u = 0; u < 4; u++) {
            const int idx = tid + (u << 8);
            const int row = idx >> 4;
            const int c4  = idx & 15;
            float4 v = *(const float4*)(bbase + row * 256 + c4 * 4);
            __nv_bfloat162 p0 = __float22bfloat162_rn(make_float2(v.x, v.y));
            __nv_bfloat162 p1 = __float22bfloat162_rn(make_float2(v.z, v.w));
            uint2 w;
            w.x = *(unsigned int*)&p0;  w.y = *(unsigned int*)&p1;
            *(uint2*)(Bsm + row * 72 + c4 * 4) = w;
        }
        __syncthreads();

        const int wm = warp & 3;
        const int wn = warp >> 2;

        float acc[2][4][4];
#pragma unroll
        for (int mi = 0; mi < 2; mi++)
#pragma unroll
            for (int ni = 0; ni < 4; ni++)
#pragma unroll
                for (int r = 0; r < 4; r++) acc[mi][ni][r] = 0.f;

        const unsigned int asmb = (unsigned int)__cvta_generic_to_shared(Asm);
        const unsigned int bsmb = (unsigned int)__cvta_generic_to_shared(Bsm);
        const int arow  = lane & 15;
        const int ahalf = lane >> 4;
        const int brow  = lane & 7;
        const int bhalf = (lane >> 3) & 1;

#pragma unroll
        for (int ks = 0; ks < 4; ks++) {
            unsigned int af[2][4];
#pragma unroll
            for (int mi = 0; mi < 2; mi++) {
                unsigned int addr = asmb
                    + (unsigned int)((wm * 32 + mi * 16 + arow) * 144)
                    + ks * 32 + ahalf * 16;
                asm volatile(
                    "ldmatrix.sync.aligned.m8n8.x4.shared.b16 {%0,%1,%2,%3}, [%4];"
                    : "=r"(af[mi][0]), "=r"(af[mi][1]),
                      "=r"(af[mi][2]), "=r"(af[mi][3])
                    : "r"(addr));
            }
#pragma unroll
            for (int ni = 0; ni < 4; ni++) {
                unsigned int bf0, bf1;
                unsigned int baddr = bsmb
                    + (unsigned int)((wn * 32 + ni * 8 + brow) * 144)
                    + ks * 32 + bhalf * 16;
                asm volatile(
                    "ldmatrix.sync.aligned.m8n8.x2.shared.b16 {%0,%1}, [%2];"
                    : "=r"(bf0), "=r"(bf1) : "r"(baddr));
#pragma unroll
                for (int mi = 0; mi < 2; mi++) {
                    asm volatile(
                        "mma.sync.aligned.m16n8k16.row.col.f32.bf16.bf16.f32 "
                        "{%0,%1,%2,%3}, {%4,%5,%6,%7}, {%8,%9}, {%0,%1,%2,%3};"
                        : "+f"(acc[mi][ni][0]), "+f"(acc[mi][ni][1]),
                          "+f"(acc[mi][ni][2]), "+f"(acc[mi][ni][3])
                        : "r"(af[mi][0]), "r"(af[mi][1]),
                          "r"(af[mi][2]), "r"(af[mi][3]),
                          "r"(bf0), "r"(bf1));
                }
            }
        }

        const int slotBase = (g << 12) + (mblk << 7) + wm * 32 + (lane >> 2);
        const int colBase  = (nblk << 6) + wn * 32 + (lane & 3) * 2;
#pragma unroll
        for (int ni = 0; ni < 4; ni++) {
            const int col = colBase + ni * 8;
            const float b0 = 0.25f * __ldg(keyb + col);
            const float b1 = 0.25f * __ldg(keyb + col + 1);
#pragma unroll
            for (int mi = 0; mi < 2; mi++) {
                __nv_bfloat162 lo = __float22bfloat162_rn(
                    make_float2(acc[mi][ni][0] + b0, acc[mi][ni][1] + b1));
                __nv_bfloat162 hi = __float22bfloat162_rn(
                    make_float2(acc[mi][ni][2] + b0, acc[mi][ni][3] + b1));
                *(unsigned int*)(g_Ktab + (size_t)(slotBase + mi * 16) * 512 + col)
                    = *(unsigned int*)&lo;
                *(unsigned int*)(g_Ktab + (size_t)(slotBase + mi * 16 + 8) * 512 + col)
                    = *(unsigned int*)&hi;
            }
        }
    }
}

// ---------------------------------------------------------------------------
// Stage 2 main kernel (proven, (128,5)).
// ---------------------------------------------------------------------------
struct Tok {
    uint2  K0, K1, K2, K3;
    float4 v0, v1, v2, v3;
    float4 q;
};

__device__ __forceinline__ float4 bf4(uint2 u) {
    float2 a = __bfloat1622float2(*reinterpret_cast<const __nv_bfloat162*>(&u.x));
    float2 b = __bfloat1622float2(*reinterpret_cast<const __nv_bfloat162*>(&u.y));
    return make_float4(a.x, a.y, b.x, b.y);
}

__global__ void __launch_bounds__(128, 5) engram_main_kernel(
    const float* __restrict__ x,        // (B,T,4,128)
    const int*   __restrict__ ids,      // (B,T)
    const int*   __restrict__ mult,     // (2,2,3)
    const float* __restrict__ wq,       // (4,128)
    const float* __restrict__ wk,       // (4,128)
    const float* __restrict__ convw,    // (512,4)
    const float* __restrict__ convn,    // (4,128)
    float*       __restrict__ out)      // (B,T,4,128)
{
    const int stream = threadIdx.x >> 5;
    const int lane   = threadIdx.x & 31;
    const int b      = blockIdx.x >> 8;
    const int chunk  = blockIdx.x & 255;
    const int t0     = chunk * R_TOK;

    const int c = stream * 128 + lane * 4;
    const int d = lane * 4;

    const float4 wq4  = *(const float4*)(wq + c);
    const float4 wk4  = *(const float4*)(wk + c);
    const float4 wqk4 = make_float4(wq4.x * wk4.x, wq4.y * wk4.y,
                                    wq4.z * wk4.z, wq4.w * wk4.w);
    const float4 cvn4 = *(const float4*)(convn + c);
    const float4 cwA  = *(const float4*)(convw + (c + 0) * 4);
    const float4 cwB  = *(const float4*)(convw + (c + 1) * 4);
    const float4 cwC  = *(const float4*)(convw + (c + 2) * 4);
    const float4 cwD  = *(const float4*)(convw + (c + 3) * 4);

    const int m00 = mult[0],  m01 = mult[1];
    const int m10 = mult[3],  m11 = mult[4];
    const int m20 = mult[6],  m21 = mult[7],  m22 = mult[8];
    const int m30 = mult[9],  m31 = mult[10], m32 = mult[11];

    const float inv128     = 0.0078125f;
    const float eps        = 1.1920929e-7f;
    const float invsqrt128 = 0.08838834764831845f;

    const int    idBase = b * Tq;
    const float* xBase  = x   + (size_t)idBase * CHq + c;
    float*       oBase  = out + (size_t)idBase * CHq + c;

    float4 h1 = make_float4(0.f, 0.f, 0.f, 0.f);
    float4 h2 = h1;
    float4 h3 = h1;

    auto gather = [&](Tok& T, int ia, int ib, int ic, int t) {
        const int h0i = (((ib * m00) ^ (ic * m01)) & 4095);
        const int h1i = (((ib * m10) ^ (ic * m11)) & 4095) + 4096;
        const int h2i = (((ia * m20) ^ (ib * m21) ^ (ic * m22)) & 4095) + 8192;
        const int h3i = (((ia * m30) ^ (ib * m31) ^ (ic * m32)) & 4095) + 12288;
        T.K0 = __ldg((const uint2*)(g_Ktab + (size_t)h0i * 512 + c));
        T.K1 = __ldg((const uint2*)(g_Ktab + (size_t)h1i * 512 + c));
        T.K2 = __ldg((const uint2*)(g_Ktab + (size_t)h2i * 512 + c));
        T.K3 = __ldg((const uint2*)(g_Ktab + (size_t)h3i * 512 + c));
        T.v0 = __ldg((const float4*)(g_Vtab + (size_t)h0i * 128 + d));
        T.v1 = __ldg((const float4*)(g_Vtab + (size_t)h1i * 128 + d));
        T.v2 = __ldg((const float4*)(g_Vtab + (size_t)h2i * 128 + d));
        T.v3 = __ldg((const float4*)(g_Vtab + (size_t)h3i * 128 + d));
        T.q  = *(const float4*)(xBase + (size_t)t * CHq);
    };

    auto compute = [&](const Tok& T, int t, bool store) {
        const float4 k0 = bf4(T.K0);
        const float4 k1 = bf4(T.K1);
        const float4 k2 = bf4(T.K2);
        const float4 k3 = bf4(T.K3);
        float4 kr, vb;
        kr.x = (k0.x + k1.x) + (k2.x + k3.x);
        kr.y = (k0.y + k1.y) + (k2.y + k3.y);
        kr.z = (k0.z + k1.z) + (k2.z + k3.z);
        kr.w = (k0.w + k1.w) + (k2.w + k3.w);
        vb.x = (T.v0.x + T.v1.x) + (T.v2.x + T.v3.x);
        vb.y = (T.v0.y + T.v1.y) + (T.v2.y + T.v3.y);
        vb.z = (T.v0.z + T.v1.z) + (T.v2.z + T.v3.z);
        vb.w = (T.v0.w + T.v1.w) + (T.v2.w + T.v3.w);

        float p0 = T.q.x * T.q.x + T.q.y * T.q.y + T.q.z * T.q.z + T.q.w * T.q.w;
        float p1 = kr.x * kr.x + kr.y * kr.y + kr.z * kr.z + kr.w * kr.w;
        float p2 = T.q.x * kr.x * wqk4.x + T.q.y * kr.y * wqk4.y
                 + T.q.z * kr.z * wqk4.z + T.q.w * kr.w * wqk4.w;
        float p3 = vb.x * vb.x + vb.y * vb.y + vb.z * vb.z + vb.w * vb.w;

        const bool lo = (lane < 16);
        float ea = __shfl_xor_sync(0xffffffffu, p0, 16);
        float eb = __shfl_xor_sync(0xffffffffu, p2, 16);
        float aa = lo ? (p0 + ea) : (p2 + eb);
        float ec = __shfl_xor_sync(0xffffffffu, p1, 16);
        float ed = __shfl_xor_sync(0xffffffffu, p3, 16);
        float bb = lo ? (p1 + ec) : (p3 + ed);
#pragma unroll
        for (int off = 8; off; off >>= 1) {
            aa += __shfl_xor_sync(0xffffffffu, aa, off);
            bb += __shfl_xor_sync(0xffffffffu, bb, off);
        }
        const float a2 = __shfl_xor_sync(0xffffffffu, aa, 16);
        const float b2 = __shfl_xor_sync(0xffffffffu, bb, 16);
        const float sq  = lo ? aa : a2;
        const float sk  = lo ? bb : b2;
        const float sqk = lo ? a2 : aa;
        const float svb = lo ? b2 : bb;

        const float rsq   = rsqrtf(sq * inv128 + eps);
        const float rsk   = rsqrtf(sk * inv128 + eps);
        const float score = sqk * rsq * rsk * invsqrt128;
        const float gate  = __fdividef(1.f, 1.f + __expf(-score));
        const float rr    = rsqrtf(gate * gate * svb * inv128 + eps) * gate;

        float4 xn;
        xn.x = vb.x * rr * cvn4.x;  xn.y = vb.y * rr * cvn4.y;
        xn.z = vb.z * rr * cvn4.z;  xn.w = vb.w * rr * cvn4.w;

        if (store) {
            float4 y;
            y.x = cwA.x * h3.x + cwA.y * h2.x + cwA.z * h1.x + cwA.w * xn.x;
            y.y = cwB.x * h3.y + cwB.y * h2.y + cwB.z * h1.y + cwB.w * xn.y;
            y.z = cwC.x * h3.z + cwC.y * h2.z + cwC.z * h1.z + cwC.w * xn.z;
            y.w = cwD.x * h3.w + cwD.y * h2.w + cwD.z * h1.w + cwD.w * xn.w;
            y.x = __fdividef(y.x, 1.f + __expf(-y.x));
            y.y = __fdividef(y.y, 1.f + __expf(-y.y));
            y.z = __fdividef(y.z, 1.f + __expf(-y.z));
            y.w = __fdividef(y.w, 1.f + __expf(-y.w));
            float4 o;
            o.x = vb.x * gate + y.x;  o.y = vb.y * gate + y.y;
            o.z = vb.z * gate + y.z;  o.w = vb.w * gate + y.w;
            *(float4*)(oBase + (size_t)t * CHq) = o;
        }
        h3 = h2; h2 = h1; h1 = xn;
    };

    int ia = (t0 - 5 >= 0) ? __ldg(ids + idBase + t0 - 5) : 0;
    int ib = (t0 - 4 >= 0) ? __ldg(ids + idBase + t0 - 4) : 0;

#pragma unroll
    for (int tt = -3; tt < 0; tt++) {
        const int t  = t0 + tt;
        const int ic = (t >= 0) ? __ldg(ids + idBase + t) : 0;
        if (t >= 0) {
            Tok P;
            gather(P, ia, ib, ic, t);
            compute(P, t, false);
        }
        ia = ib; ib = ic;
    }

    int ic = __ldg(ids + idBase + t0);
    Tok cur;
    gather(cur, ia, ib, ic, t0);

    for (int tt = 0; tt < R_TOK; tt++) {
        const int t = t0 + tt;
        Tok nxt;
        int in_ = ic;
        if (tt + 1 < R_TOK) {
            in_ = __ldg(ids + idBase + t + 1);
            gather(nxt, ib, ic, in_, t + 1);
        }
        compute(cur, t, true);
        ia = ib; ib = ic; ic = in_;
        cur = nxt;
    }
}

// ---------------------------------------------------------------------------
extern "C" void kernel_launch(void* const* d_in, const int* in_sizes, int n_in,
                              void* d_out, int out_size)
{
    const float* x          = (const float*)d_in[0];
    const int*   input_ids  = (const int*)  d_in[1];
    const int*   multipliers= (const int*)  d_in[2];
    const float* embedding  = (const float*)d_in[3];
    const float* val_W      = (const float*)d_in[4];
    const float* val_b      = (const float*)d_in[5];
    const float* key_W      = (const float*)d_in[6];
    const float* key_b      = (const float*)d_in[7];
    const float* normq_w    = (const float*)d_in[8];
    const float* normk_w    = (const float*)d_in[9];
    const float* conv_w     = (const float*)d_in[10];
    const float* convnorm_w = (const float*)d_in[11];
    float* out = (float*)d_out;

    precompute_kernel<<<1536, 256>>>(embedding, val_W, val_b, key_W, key_b);

    engram_main_kernel<<<Bq * CHUNKS, 128>>>(
        x, input_ids, multipliers,
        normq_w, normk_w, conv_w, convnorm_w, out);
}

// round 16
// speedup vs baseline: 1.2890x; 1.0087x over previous
#include <cuda_runtime.h>
#include <cuda_bf16.h>

// ---------------------------------------------------------------------------
// EngramModule fused forward.
// Stage 1 (merged launch, 1536 blocks, 1:2 V:K interleave):
//   blockIdx.x % 3 == 0 -> V table tile (64x64, split-bf16 HMMA, ~fp32 exact)
//   else                -> K table tile (128x64, bf16 HMMA)
// Stage 2: main fused kernel with packed f32x2 arithmetic in the per-token
//          tail (bit-exact fp32, ~2x fewer FMA-pipe instructions there).
// ---------------------------------------------------------------------------

#define Bq    8
#define Tq    4096
#define CHq   512
#define R_TOK 16
#define CHUNKS (Tq / R_TOK)   // 256

__device__ float         g_Vtab[16384 * 128];   // 8 MB fp32
__device__ __nv_bfloat16 g_Ktab[16384 * 512];   // 16 MB bf16

typedef unsigned long long u64;

__device__ __forceinline__ u64 f2_pack(float lo, float hi) {
    u64 r; asm("mov.b64 %0, {%1, %2};" : "=l"(r) : "f"(lo), "f"(hi)); return r;
}
__device__ __forceinline__ float2 f2_unpack(u64 v) {
    float2 r; asm("mov.b64 {%0, %1}, %2;" : "=f"(r.x), "=f"(r.y) : "l"(v)); return r;
}
__device__ __forceinline__ u64 f2_add(u64 a, u64 b) {
    u64 r; asm("add.rn.f32x2 %0, %1, %2;" : "=l"(r) : "l"(a), "l"(b)); return r;
}
__device__ __forceinline__ u64 f2_mul(u64 a, u64 b) {
    u64 r; asm("mul.rn.f32x2 %0, %1, %2;" : "=l"(r) : "l"(a), "l"(b)); return r;
}
__device__ __forceinline__ u64 f2_fma(u64 a, u64 b, u64 c) {
    u64 r; asm("fma.rn.f32x2 %0, %1, %2, %3;" : "=l"(r) : "l"(a), "l"(b), "l"(c)); return r;
}

// ---------------------------------------------------------------------------
// Stage 1: merged precompute (unchanged R15, measured ~16.5us).
// ---------------------------------------------------------------------------
__global__ void __launch_bounds__(256) precompute_kernel(
    const float* __restrict__ emb,      // (16384, 64)
    const float* __restrict__ valW,     // (128, 256)
    const float* __restrict__ valb,     // (128)
    const float* __restrict__ keyW,     // (512, 256)
    const float* __restrict__ keyb)     // (512)
{
    __shared__ __align__(16) char smem_raw[36864];

    const int tid  = threadIdx.x;
    const int bx   = blockIdx.x;
    const int warp = tid >> 5;
    const int lane = tid & 31;

    if (bx % 3 == 0) {
        // ============ V path: split-bf16 HMMA, 64 slots x 64 cols ============
        const int vIdx = bx / 3;
        const int nblk = vIdx & 1;
        const int mblk = (vIdx >> 1) & 63;
        const int g    = vIdx >> 7;

        __nv_bfloat16* Ahi = (__nv_bfloat16*)(smem_raw);
        __nv_bfloat16* Alo = (__nv_bfloat16*)(smem_raw + 9216);
        __nv_bfloat16* Bhi = (__nv_bfloat16*)(smem_raw + 18432);
        __nv_bfloat16* Blo = (__nv_bfloat16*)(smem_raw + 27648);

        const float* abase = emb  + (size_t)((g << 12) + (mblk << 6)) * 64;
        const float* bbase = valW + (size_t)(nblk << 6) * 256 + g * 64;
#pragma unroll
        for (int u = 0; u < 4; u++) {
            const int idx = tid + (u << 8);
            const int row = idx >> 4;
            const int c4  = idx & 15;

            float4 va = *(const float4*)(abase + row * 64 + c4 * 4);
            float4 vb = *(const float4*)(bbase + row * 256 + c4 * 4);

            __nv_bfloat162 ah0 = __float22bfloat162_rn(make_float2(va.x, va.y));
            __nv_bfloat162 ah1 = __float22bfloat162_rn(make_float2(va.z, va.w));
            __nv_bfloat162 al0 = __float22bfloat162_rn(make_float2(
                va.x - __bfloat162float(__low2bfloat16(ah0)),
                va.y - __bfloat162float(__high2bfloat16(ah0))));
            __nv_bfloat162 al1 = __float22bfloat162_rn(make_float2(
                va.z - __bfloat162float(__low2bfloat16(ah1)),
                va.w - __bfloat162float(__high2bfloat16(ah1))));
            __nv_bfloat162 bh0 = __float22bfloat162_rn(make_float2(vb.x, vb.y));
            __nv_bfloat162 bh1 = __float22bfloat162_rn(make_float2(vb.z, vb.w));
            __nv_bfloat162 bl0 = __float22bfloat162_rn(make_float2(
                vb.x - __bfloat162float(__low2bfloat16(bh0)),
                vb.y - __bfloat162float(__high2bfloat16(bh0))));
            __nv_bfloat162 bl1 = __float22bfloat162_rn(make_float2(
                vb.z - __bfloat162float(__low2bfloat16(bh1)),
                vb.w - __bfloat162float(__high2bfloat16(bh1))));

            uint2 w;
            w.x = *(unsigned int*)&ah0;  w.y = *(unsigned int*)&ah1;
            *(uint2*)(Ahi + row * 72 + c4 * 4) = w;
            w.x = *(unsigned int*)&al0;  w.y = *(unsigned int*)&al1;
            *(uint2*)(Alo + row * 72 + c4 * 4) = w;
            w.x = *(unsigned int*)&bh0;  w.y = *(unsigned int*)&bh1;
            *(uint2*)(Bhi + row * 72 + c4 * 4) = w;
            w.x = *(unsigned int*)&bl0;  w.y = *(unsigned int*)&bl1;
            *(uint2*)(Blo + row * 72 + c4 * 4) = w;
        }
        __syncthreads();

        const int wm = warp & 3;
        const int wn = warp >> 2;

        float acc[4][4];
#pragma unroll
        for (int ni = 0; ni < 4; ni++)
#pragma unroll
            for (int r = 0; r < 4; r++) acc[ni][r] = 0.f;

        const unsigned int ahib = (unsigned int)__cvta_generic_to_shared(Ahi);
        const unsigned int alob = (unsigned int)__cvta_generic_to_shared(Alo);
        const unsigned int bhib = (unsigned int)__cvta_generic_to_shared(Bhi);
        const unsigned int blob = (unsigned int)__cvta_generic_to_shared(Blo);
        const int arow  = lane & 15;
        const int ahalf = lane >> 4;
        const int brow  = lane & 7;
        const int bhalf = (lane >> 3) & 1;

#pragma unroll
        for (int ks = 0; ks < 4; ks++) {
            const unsigned int aoff =
                (unsigned int)((wm * 16 + arow) * 144) + ks * 32 + ahalf * 16;
            unsigned int ah[4], al[4];
            asm volatile(
                "ldmatrix.sync.aligned.m8n8.x4.shared.b16 {%0,%1,%2,%3}, [%4];"
                : "=r"(ah[0]), "=r"(ah[1]), "=r"(ah[2]), "=r"(ah[3])
                : "r"(ahib + aoff));
            asm volatile(
                "ldmatrix.sync.aligned.m8n8.x4.shared.b16 {%0,%1,%2,%3}, [%4];"
                : "=r"(al[0]), "=r"(al[1]), "=r"(al[2]), "=r"(al[3])
                : "r"(alob + aoff));
#pragma unroll
            for (int ni = 0; ni < 4; ni++) {
                const unsigned int boff =
                    (unsigned int)((wn * 32 + ni * 8 + brow) * 144)
                    + ks * 32 + bhalf * 16;
                unsigned int bh0, bh1, bl0, bl1;
                asm volatile(
                    "ldmatrix.sync.aligned.m8n8.x2.shared.b16 {%0,%1}, [%2];"
                    : "=r"(bh0), "=r"(bh1) : "r"(bhib + boff));
                asm volatile(
                    "ldmatrix.sync.aligned.m8n8.x2.shared.b16 {%0,%1}, [%2];"
                    : "=r"(bl0), "=r"(bl1) : "r"(blob + boff));
                asm volatile(
                    "mma.sync.aligned.m16n8k16.row.col.f32.bf16.bf16.f32 "
                    "{%0,%1,%2,%3}, {%4,%5,%6,%7}, {%8,%9}, {%0,%1,%2,%3};"
                    : "+f"(acc[ni][0]), "+f"(acc[ni][1]),
                      "+f"(acc[ni][2]), "+f"(acc[ni][3])
                    : "r"(ah[0]), "r"(ah[1]), "r"(ah[2]), "r"(ah[3]),
                      "r"(bh0), "r"(bh1));
                asm volatile(
                    "mma.sync.aligned.m16n8k16.row.col.f32.bf16.bf16.f32 "
                    "{%0,%1,%2,%3}, {%4,%5,%6,%7}, {%8,%9}, {%0,%1,%2,%3};"
                    : "+f"(acc[ni][0]), "+f"(acc[ni][1]),
                      "+f"(acc[ni][2]), "+f"(acc[ni][3])
                    : "r"(ah[0]), "r"(ah[1]), "r"(ah[2]), "r"(ah[3]),
                      "r"(bl0), "r"(bl1));
                asm volatile(
                    "mma.sync.aligned.m16n8k16.row.col.f32.bf16.bf16.f32 "
                    "{%0,%1,%2,%3}, {%4,%5,%6,%7}, {%8,%9}, {%0,%1,%2,%3};"
                    : "+f"(acc[ni][0]), "+f"(acc[ni][1]),
                      "+f"(acc[ni][2]), "+f"(acc[ni][3])
                    : "r"(al[0]), "r"(al[1]), "r"(al[2]), "r"(al[3]),
                      "r"(bh0), "r"(bh1));
            }
        }

        const int slotBase = (g << 12) + (mblk << 6) + wm * 16 + (lane >> 2);
        const int colBase  = (nblk << 6) + wn * 32 + (lane & 3) * 2;
#pragma unroll
        for (int ni = 0; ni < 4; ni++) {
            const int col = colBase + ni * 8;
            const float b0 = 0.25f * __ldg(valb + col);
            const float b1 = 0.25f * __ldg(valb + col + 1);
            *(float2*)(g_Vtab + (size_t)slotBase * 128 + col)
                = make_float2(acc[ni][0] + b0, acc[ni][1] + b1);
            *(float2*)(g_Vtab + (size_t)(slotBase + 8) * 128 + col)
                = make_float2(acc[ni][2] + b0, acc[ni][3] + b1);
        }
    } else {
        // ============ K path: bf16 HMMA, 128 slots x 64 cols ============
        const int kIdx = (bx / 3) * 2 + (bx % 3) - 1;
        const int nblk = kIdx & 7;
        const int mblk = (kIdx >> 3) & 31;
        const int g    = kIdx >> 8;

        __nv_bfloat16* Asm = (__nv_bfloat16*)(smem_raw);
        __nv_bfloat16* Bsm = (__nv_bfloat16*)(smem_raw + 18432);

        const float* abase = emb + (size_t)((g << 12) + (mblk << 7)) * 64;
#pragma unroll
        for (int u = 0; u < 8; u++) {
            const int idx = tid + (u << 8);
            const int row = idx >> 4;
            const int c4  = idx & 15;
            float4 v = *(const float4*)(abase + row * 64 + c4 * 4);
            __nv_bfloat162 p0 = __float22bfloat162_rn(make_float2(v.x, v.y));
            __nv_bfloat162 p1 = __float22bfloat162_rn(make_float2(v.z, v.w));
            uint2 w;
            w.x = *(unsigned int*)&p0;  w.y = *(unsigned int*)&p1;
            *(uint2*)(Asm + row * 72 + c4 * 4) = w;
        }
        const float* bbase = keyW + (size_t)(nblk << 6) * 256 + g * 64;
#pragma unroll
        for (int u = 0; u < 4; u++) {
            const int idx = tid + (u << 8);
            const int row = idx >> 4;
            const int c4  = idx & 15;
            float4 v = *(const float4*)(bbase + row * 256 + c4 * 4);
            __nv_bfloat162 p0 = __float22bfloat162_rn(make_float2(v.x, v.y));
            __nv_bfloat162 p1 = __float22bfloat162_rn(make_float2(v.z, v.w));
            uint2 w;
            w.x = *(unsigned int*)&p0;  w.y = *(unsigned int*)&p1;
            *(uint2*)(Bsm + row * 72 + c4 * 4) = w;
        }
        __syncthreads();

        const int wm = warp & 3;
        const int wn = warp >> 2;

        float acc[2][4][4];
#pragma unroll
        for (int mi = 0; mi < 2; mi++)
#pragma unroll
            for (int ni = 0; ni < 4; ni++)
#pragma unroll
                for (int r = 0; r < 4; r++) acc[mi][ni][r] = 0.f;

        const unsigned int asmb = (unsigned int)__cvta_generic_to_shared(Asm);
        const unsigned int bsmb = (unsigned int)__cvta_generic_to_shared(Bsm);
        const int arow  = lane & 15;
        const int ahalf = lane >> 4;
        const int brow  = lane & 7;
        const int bhalf = (lane >> 3) & 1;

#pragma unroll
        for (int ks = 0; ks < 4; ks++) {
            unsigned int af[2][4];
#pragma unroll
            for (int mi = 0; mi < 2; mi++) {
                unsigned int addr = asmb
                    + (unsigned int)((wm * 32 + mi * 16 + arow) * 144)
                    + ks * 32 + ahalf * 16;
                asm volatile(
                    "ldmatrix.sync.aligned.m8n8.x4.shared.b16 {%0,%1,%2,%3}, [%4];"
                    : "=r"(af[mi][0]), "=r"(af[mi][1]),
                      "=r"(af[mi][2]), "=r"(af[mi][3])
                    : "r"(addr));
            }
#pragma unroll
            for (int ni = 0; ni < 4; ni++) {
                unsigned int bf0, bf1;
                unsigned int baddr = bsmb
                    + (unsigned int)((wn * 32 + ni * 8 + brow) * 144)
                    + ks * 32 + bhalf * 16;
                asm volatile(
                    "ldmatrix.sync.aligned.m8n8.x2.shared.b16 {%0,%1}, [%2];"
                    : "=r"(bf0), "=r"(bf1) : "r"(baddr));
#pragma unroll
                for (int mi = 0; mi < 2; mi++) {
                    asm volatile(
                        "mma.sync.aligned.m16n8k16.row.col.f32.bf16.bf16.f32 "
                        "{%0,%1,%2,%3}, {%4,%5,%6,%7}, {%8,%9}, {%0,%1,%2,%3};"
                        : "+f"(acc[mi][ni][0]), "+f"(acc[mi][ni][1]),
                          "+f"(acc[mi][ni][2]), "+f"(acc[mi][ni][3])
                        : "r"(af[mi][0]), "r"(af[mi][1]),
                          "r"(af[mi][2]), "r"(af[mi][3]),
                          "r"(bf0), "r"(bf1));
                }
            }
        }

        const int slotBase = (g << 12) + (mblk << 7) + wm * 32 + (lane >> 2);
        const int colBase  = (nblk << 6) + wn * 32 + (lane & 3) * 2;
#pragma unroll
        for (int ni = 0; ni < 4; ni++) {
            const int col = colBase + ni * 8;
            const float b0 = 0.25f * __ldg(keyb + col);
            const float b1 = 0.25f * __ldg(keyb + col + 1);
#pragma unroll
            for (int mi = 0; mi < 2; mi++) {
                __nv_bfloat162 lo = __float22bfloat162_rn(
                    make_float2(acc[mi][ni][0] + b0, acc[mi][ni][1] + b1));
                __nv_bfloat162 hi = __float22bfloat162_rn(
                    make_float2(acc[mi][ni][2] + b0, acc[mi][ni][3] + b1));
                *(unsigned int*)(g_Ktab + (size_t)(slotBase + mi * 16) * 512 + col)
                    = *(unsigned int*)&lo;
                *(unsigned int*)(g_Ktab + (size_t)(slotBase + mi * 16 + 8) * 512 + col)
                    = *(unsigned int*)&hi;
            }
        }
    }
}

// ---------------------------------------------------------------------------
// Stage 2 main kernel: packed f32x2 tail.
// ---------------------------------------------------------------------------
struct Tok {
    uint2      K0, K1, K2, K3;     // bf16x2 pairs (4 values per K row)
    ulonglong2 v0, v1, v2, v3;     // fp32 pairs (4 values per V row)
    float4     q;
};

__global__ void __launch_bounds__(128, 5) engram_main_kernel(
    const float* __restrict__ x,        // (B,T,4,128)
    const int*   __restrict__ ids,      // (B,T)
    const int*   __restrict__ mult,     // (2,2,3)
    const float* __restrict__ wq,       // (4,128)
    const float* __restrict__ wk,       // (4,128)
    const float* __restrict__ convw,    // (512,4)
    const float* __restrict__ convn,    // (4,128)
    float*       __restrict__ out)      // (B,T,4,128)
{
    const int stream = threadIdx.x >> 5;
    const int lane   = threadIdx.x & 31;
    const int b      = blockIdx.x >> 8;
    const int chunk  = blockIdx.x & 255;
    const int t0     = chunk * R_TOK;

    const int c = stream * 128 + lane * 4;
    const int d = lane * 4;

    const float4 wq4  = *(const float4*)(wq + c);
    const float4 wk4  = *(const float4*)(wk + c);
    const float4 wqk4 = make_float4(wq4.x * wk4.x, wq4.y * wk4.y,
                                    wq4.z * wk4.z, wq4.w * wk4.w);
    // packed conv-norm weights
    const ulonglong2 cvnP = *(const ulonglong2*)(convn + c);
    // conv taps: per-channel rows; pack tap j across channel pairs
    const float4 cwA = *(const float4*)(convw + (c + 0) * 4);
    const float4 cwB = *(const float4*)(convw + (c + 1) * 4);
    const float4 cwC = *(const float4*)(convw + (c + 2) * 4);
    const float4 cwD = *(const float4*)(convw + (c + 3) * 4);
    const u64 w0a = f2_pack(cwA.x, cwB.x), w0b = f2_pack(cwC.x, cwD.x);
    const u64 w1a = f2_pack(cwA.y, cwB.y), w1b = f2_pack(cwC.y, cwD.y);
    const u64 w2a = f2_pack(cwA.z, cwB.z), w2b = f2_pack(cwC.z, cwD.z);
    const u64 w3a = f2_pack(cwA.w, cwB.w), w3b = f2_pack(cwC.w, cwD.w);

    const int m00 = mult[0],  m01 = mult[1];
    const int m10 = mult[3],  m11 = mult[4];
    const int m20 = mult[6],  m21 = mult[7],  m22 = mult[8];
    const int m30 = mult[9],  m31 = mult[10], m32 = mult[11];

    const float inv128     = 0.0078125f;
    const float eps        = 1.1920929e-7f;
    const float invsqrt128 = 0.08838834764831845f;

    const int    idBase = b * Tq;
    const float* xBase  = x   + (size_t)idBase * CHq + c;
    float*       oBase  = out + (size_t)idBase * CHq + c;

    u64 h1a = 0, h1b = 0, h2a = 0, h2b = 0, h3a = 0, h3b = 0;  // xn history

    auto gather = [&](Tok& T, int ia, int ib, int ic, int t) {
        const int h0i = (((ib * m00) ^ (ic * m01)) & 4095);
        const int h1i = (((ib * m10) ^ (ic * m11)) & 4095) + 4096;
        const int h2i = (((ia * m20) ^ (ib * m21) ^ (ic * m22)) & 4095) + 8192;
        const int h3i = (((ia * m30) ^ (ib * m31) ^ (ic * m32)) & 4095) + 12288;
        T.K0 = __ldg((const uint2*)(g_Ktab + (size_t)h0i * 512 + c));
        T.K1 = __ldg((const uint2*)(g_Ktab + (size_t)h1i * 512 + c));
        T.K2 = __ldg((const uint2*)(g_Ktab + (size_t)h2i * 512 + c));
        T.K3 = __ldg((const uint2*)(g_Ktab + (size_t)h3i * 512 + c));
        T.v0 = __ldg((const ulonglong2*)(g_Vtab + (size_t)h0i * 128 + d));
        T.v1 = __ldg((const ulonglong2*)(g_Vtab + (size_t)h1i * 128 + d));
        T.v2 = __ldg((const ulonglong2*)(g_Vtab + (size_t)h2i * 128 + d));
        T.v3 = __ldg((const ulonglong2*)(g_Vtab + (size_t)h3i * 128 + d));
        T.q  = *(const float4*)(xBase + (size_t)t * CHq);
    };

    auto compute = [&](const Tok& T, int t, bool store) {
        // K sum: scalar (cvt outputs are scalar floats)
        float2 k0a = __bfloat1622float2(*(const __nv_bfloat162*)&T.K0.x);
        float2 k0b = __bfloat1622float2(*(const __nv_bfloat162*)&T.K0.y);
        float2 k1a = __bfloat1622float2(*(const __nv_bfloat162*)&T.K1.x);
        float2 k1b = __bfloat1622float2(*(const __nv_bfloat162*)&T.K1.y);
        float2 k2a = __bfloat1622float2(*(const __nv_bfloat162*)&T.K2.x);
        float2 k2b = __bfloat1622float2(*(const __nv_bfloat162*)&T.K2.y);
        float2 k3a = __bfloat1622float2(*(const __nv_bfloat162*)&T.K3.x);
        float2 k3b = __bfloat1622float2(*(const __nv_bfloat162*)&T.K3.y);
        float4 kr;
        kr.x = (k0a.x + k1a.x) + (k2a.x + k3a.x);
        kr.y = (k0a.y + k1a.y) + (k2a.y + k3a.y);
        kr.z = (k0b.x + k1b.x) + (k2b.x + k3b.x);
        kr.w = (k0b.y + k1b.y) + (k2b.y + k3b.y);

        // V sum: packed
        const u64 vbA = f2_add(f2_add(T.v0.x, T.v1.x), f2_add(T.v2.x, T.v3.x));
        const u64 vbB = f2_add(f2_add(T.v0.y, T.v1.y), f2_add(T.v2.y, T.v3.y));

        // p3 = |vb|^2 : packed dot
        u64 t3 = f2_mul(vbA, vbA);
        t3 = f2_fma(vbB, vbB, t3);
        float2 t3u = f2_unpack(t3);
        float p3 = t3u.x + t3u.y;

        float p0 = T.q.x * T.q.x + T.q.y * T.q.y + T.q.z * T.q.z + T.q.w * T.q.w;
        float p1 = kr.x * kr.x + kr.y * kr.y + kr.z * kr.z + kr.w * kr.w;
        float p2 = T.q.x * kr.x * wqk4.x + T.q.y * kr.y * wqk4.y
                 + T.q.z * kr.z * wqk4.z + T.q.w * kr.w * wqk4.w;

        const bool lo = (lane < 16);
        float ea = __shfl_xor_sync(0xffffffffu, p0, 16);
        float eb = __shfl_xor_sync(0xffffffffu, p2, 16);
        float aa = lo ? (p0 + ea) : (p2 + eb);
        float ec = __shfl_xor_sync(0xffffffffu, p1, 16);
        float ed = __shfl_xor_sync(0xffffffffu, p3, 16);
        float bb = lo ? (p1 + ec) : (p3 + ed);
#pragma unroll
        for (int off = 8; off; off >>= 1) {
            aa += __shfl_xor_sync(0xffffffffu, aa, off);
            bb += __shfl_xor_sync(0xffffffffu, bb, off);
        }
        const float a2 = __shfl_xor_sync(0xffffffffu, aa, 16);
        const float b2 = __shfl_xor_sync(0xffffffffu, bb, 16);
        const float sq  = lo ? aa : a2;
        const float sk  = lo ? bb : b2;
        const float sqk = lo ? a2 : aa;
        const float svb = lo ? b2 : bb;

        const float rsq   = rsqrtf(sq * inv128 + eps);
        const float rsk   = rsqrtf(sk * inv128 + eps);
        const float score = sqk * rsq * rsk * invsqrt128;
        const float gate  = __fdividef(1.f, 1.f + __expf(-score));
        const float rr    = rsqrtf(gate * gate * svb * inv128 + eps) * gate;

        // xn = vb * rr * cvn  (packed)
        const u64 rr2 = f2_pack(rr, rr);
        const u64 xnA = f2_mul(f2_mul(vbA, rr2), cvnP.x);
        const u64 xnB = f2_mul(f2_mul(vbB, rr2), cvnP.y);

        if (store) {
            // depthwise conv (packed): y = w0*h3 + w1*h2 + w2*h1 + w3*xn
            u64 yA = f2_mul(w3a, xnA);
            yA = f2_fma(w2a, h1a, yA);
            yA = f2_fma(w1a, h2a, yA);
            yA = f2_fma(w0a, h3a, yA);
            u64 yB = f2_mul(w3b, xnB);
            yB = f2_fma(w2b, h1b, yB);
            yB = f2_fma(w1b, h2b, yB);
            yB = f2_fma(w0b, h3b, yB);

            float2 ya = f2_unpack(yA);
            float2 yb = f2_unpack(yB);
            ya.x = __fdividef(ya.x, 1.f + __expf(-ya.x));
            ya.y = __fdividef(ya.y, 1.f + __expf(-ya.y));
            yb.x = __fdividef(yb.x, 1.f + __expf(-yb.x));
            yb.y = __fdividef(yb.y, 1.f + __expf(-yb.y));

            // o = vb * gate + y (packed)
            const u64 gate2 = f2_pack(gate, gate);
            ulonglong2 o;
            o.x = f2_fma(vbA, gate2, f2_pack(ya.x, ya.y));
            o.y = f2_fma(vbB, gate2, f2_pack(yb.x, yb.y));
            *(ulonglong2*)(oBase + (size_t)t * CHq) = o;
        }
        h3a = h2a; h3b = h2b;
        h2a = h1a; h2b = h1b;
        h1a = xnA; h1b = xnB;
    };

    int ia = (t0 - 5 >= 0) ? __ldg(ids + idBase + t0 - 5) : 0;
    int ib = (t0 - 4 >= 0) ? __ldg(ids + idBase + t0 - 4) : 0;

    // ---- halo prologue: tokens t0-3 .. t0-1 (no store) ----
#pragma unroll
    for (int tt = -3; tt < 0; tt++) {
        const int t  = t0 + tt;
        const int ic = (t >= 0) ? __ldg(ids + idBase + t) : 0;
        if (t >= 0) {
            Tok P;
            gather(P, ia, ib, ic, t);
            compute(P, t, false);
        }
        ia = ib; ib = ic;
    }

    // ---- pipelined main loop ----
    int ic = __ldg(ids + idBase + t0);
    Tok cur;
    gather(cur, ia, ib, ic, t0);

    for (int tt = 0; tt < R_TOK; tt++) {
        const int t = t0 + tt;
        Tok nxt;
        int in_ = ic;
        if (tt + 1 < R_TOK) {
            in_ = __ldg(ids + idBase + t + 1);
            gather(nxt, ib, ic, in_, t + 1);
        }
        compute(cur, t, true);
        ia = ib; ib = ic; ic = in_;
        cur = nxt;
    }
}

// ---------------------------------------------------------------------------
extern "C" void kernel_launch(void* const* d_in, const int* in_sizes, int n_in,
                              void* d_out, int out_size)
{
    const float* x          = (const float*)d_in[0];
    const int*   input_ids  = (const int*)  d_in[1];
    const int*   multipliers= (const int*)  d_in[2];
    const float* embedding  = (const float*)d_in[3];
    const float* val_W      = (const float*)d_in[4];
    const float* val_b      = (const float*)d_in[5];
    const float* key_W      = (const float*)d_in[6];
    const float* key_b      = (const float*)d_in[7];
    const float* normq_w    = (const float*)d_in[8];
    const float* normk_w    = (const float*)d_in[9];
    const float* conv_w     = (const float*)d_in[10];
    const float* convnorm_w = (const float*)d_in[11];
    float* out = (float*)d_out;

    precompute_kernel<<<1536, 256>>>(embedding, val_W, val_b, key_W, key_b);

    engram_main_kernel<<<Bq * CHUNKS, 128>>>(
        x, input_ids, multipliers,
        normq_w, normk_w, conv_w, convnorm_w, out);
}

// round 17
// speedup vs baseline: 1.2901x; 1.0009x over previous
#include <cuda_runtime.h>
#include <cuda_bf16.h>

// ---------------------------------------------------------------------------
// EngramModule fused forward.
// Stage 1 (merged launch, 1024 blocks, 1:1 V:K interleave):
//   even blockIdx.x -> V table tile (64x64, split-bf16 HMMA, ~fp32 exact)
//   odd  blockIdx.x -> K table tile (128x128, bf16 HMMA)
// Stage 2: main fused kernel (R16, packed f32x2 tail).
// ---------------------------------------------------------------------------

#define Bq    8
#define Tq    4096
#define CHq   512
#define R_TOK 16
#define CHUNKS (Tq / R_TOK)   // 256

__device__ float         g_Vtab[16384 * 128];   // 8 MB fp32
__device__ __nv_bfloat16 g_Ktab[16384 * 512];   // 16 MB bf16

typedef unsigned long long u64;

__device__ __forceinline__ u64 f2_pack(float lo, float hi) {
    u64 r; asm("mov.b64 %0, {%1, %2};" : "=l"(r) : "f"(lo), "f"(hi)); return r;
}
__device__ __forceinline__ float2 f2_unpack(u64 v) {
    float2 r; asm("mov.b64 {%0, %1}, %2;" : "=f"(r.x), "=f"(r.y) : "l"(v)); return r;
}
__device__ __forceinline__ u64 f2_add(u64 a, u64 b) {
    u64 r; asm("add.rn.f32x2 %0, %1, %2;" : "=l"(r) : "l"(a), "l"(b)); return r;
}
__device__ __forceinline__ u64 f2_mul(u64 a, u64 b) {
    u64 r; asm("mul.rn.f32x2 %0, %1, %2;" : "=l"(r) : "l"(a), "l"(b)); return r;
}
__device__ __forceinline__ u64 f2_fma(u64 a, u64 b, u64 c) {
    u64 r; asm("fma.rn.f32x2 %0, %1, %2, %3;" : "=l"(r) : "l"(a), "l"(b), "l"(c)); return r;
}

// ---------------------------------------------------------------------------
// Stage 1: merged precompute. 256 threads; smem union 36864 B; 2 blocks/SM.
// ---------------------------------------------------------------------------
__global__ void __launch_bounds__(256, 2) precompute_kernel(
    const float* __restrict__ emb,      // (16384, 64)
    const float* __restrict__ valW,     // (128, 256)
    const float* __restrict__ valb,     // (128)
    const float* __restrict__ keyW,     // (512, 256)
    const float* __restrict__ keyb)     // (512)
{
    __shared__ __align__(16) char smem_raw[36864];

    const int tid  = threadIdx.x;
    const int bx   = blockIdx.x;
    const int warp = tid >> 5;
    const int lane = tid & 31;

    if ((bx & 1) == 0) {
        // ============ V path: split-bf16 HMMA, 64 slots x 64 cols ============
        const int vIdx = bx >> 1;           // 0..511
        const int nblk = vIdx & 1;
        const int mblk = (vIdx >> 1) & 63;
        const int g    = vIdx >> 7;

        __nv_bfloat16* Ahi = (__nv_bfloat16*)(smem_raw);
        __nv_bfloat16* Alo = (__nv_bfloat16*)(smem_raw + 9216);
        __nv_bfloat16* Bhi = (__nv_bfloat16*)(smem_raw + 18432);
        __nv_bfloat16* Blo = (__nv_bfloat16*)(smem_raw + 27648);

        const float* abase = emb  + (size_t)((g << 12) + (mblk << 6)) * 64;
        const float* bbase = valW + (size_t)(nblk << 6) * 256 + g * 64;
#pragma unroll
        for (int u = 0; u < 4; u++) {
            const int idx = tid + (u << 8);     // 0..1023
            const int row = idx >> 4;           // 0..63
            const int c4  = idx & 15;

            float4 va = *(const float4*)(abase + row * 64 + c4 * 4);
            float4 vb = *(const float4*)(bbase + row * 256 + c4 * 4);

            __nv_bfloat162 ah0 = __float22bfloat162_rn(make_float2(va.x, va.y));
            __nv_bfloat162 ah1 = __float22bfloat162_rn(make_float2(va.z, va.w));
            __nv_bfloat162 al0 = __float22bfloat162_rn(make_float2(
                va.x - __bfloat162float(__low2bfloat16(ah0)),
                va.y - __bfloat162float(__high2bfloat16(ah0))));
            __nv_bfloat162 al1 = __float22bfloat162_rn(make_float2(
                va.z - __bfloat162float(__low2bfloat16(ah1)),
                va.w - __bfloat162float(__high2bfloat16(ah1))));
            __nv_bfloat162 bh0 = __float22bfloat162_rn(make_float2(vb.x, vb.y));
            __nv_bfloat162 bh1 = __float22bfloat162_rn(make_float2(vb.z, vb.w));
            __nv_bfloat162 bl0 = __float22bfloat162_rn(make_float2(
                vb.x - __bfloat162float(__low2bfloat16(bh0)),
                vb.y - __bfloat162float(__high2bfloat16(bh0))));
            __nv_bfloat162 bl1 = __float22bfloat162_rn(make_float2(
                vb.z - __bfloat162float(__low2bfloat16(bh1)),
                vb.w - __bfloat162float(__high2bfloat16(bh1))));

            uint2 w;
            w.x = *(unsigned int*)&ah0;  w.y = *(unsigned int*)&ah1;
            *(uint2*)(Ahi + row * 72 + c4 * 4) = w;
            w.x = *(unsigned int*)&al0;  w.y = *(unsigned int*)&al1;
            *(uint2*)(Alo + row * 72 + c4 * 4) = w;
            w.x = *(unsigned int*)&bh0;  w.y = *(unsigned int*)&bh1;
            *(uint2*)(Bhi + row * 72 + c4 * 4) = w;
            w.x = *(unsigned int*)&bl0;  w.y = *(unsigned int*)&bl1;
            *(uint2*)(Blo + row * 72 + c4 * 4) = w;
        }
        __syncthreads();

        const int wm = warp & 3;
        const int wn = warp >> 2;

        float acc[4][4];
#pragma unroll
        for (int ni = 0; ni < 4; ni++)
#pragma unroll
            for (int r = 0; r < 4; r++) acc[ni][r] = 0.f;

        const unsigned int ahib = (unsigned int)__cvta_generic_to_shared(Ahi);
        const unsigned int alob = (unsigned int)__cvta_generic_to_shared(Alo);
        const unsigned int bhib = (unsigned int)__cvta_generic_to_shared(Bhi);
        const unsigned int blob = (unsigned int)__cvta_generic_to_shared(Blo);
        const int arow  = lane & 15;
        const int ahalf = lane >> 4;
        const int brow  = lane & 7;
        const int bhalf = (lane >> 3) & 1;

#pragma unroll
        for (int ks = 0; ks < 4; ks++) {
            const unsigned int aoff =
                (unsigned int)((wm * 16 + arow) * 144) + ks * 32 + ahalf * 16;
            unsigned int ah[4], al[4];
            asm volatile(
                "ldmatrix.sync.aligned.m8n8.x4.shared.b16 {%0,%1,%2,%3}, [%4];"
                : "=r"(ah[0]), "=r"(ah[1]), "=r"(ah[2]), "=r"(ah[3])
                : "r"(ahib + aoff));
            asm volatile(
                "ldmatrix.sync.aligned.m8n8.x4.shared.b16 {%0,%1,%2,%3}, [%4];"
                : "=r"(al[0]), "=r"(al[1]), "=r"(al[2]), "=r"(al[3])
                : "r"(alob + aoff));
#pragma unroll
            for (int ni = 0; ni < 4; ni++) {
                const unsigned int boff =
                    (unsigned int)((wn * 32 + ni * 8 + brow) * 144)
                    + ks * 32 + bhalf * 16;
                unsigned int bh0, bh1, bl0, bl1;
                asm volatile(
                    "ldmatrix.sync.aligned.m8n8.x2.shared.b16 {%0,%1}, [%2];"
                    : "=r"(bh0), "=r"(bh1) : "r"(bhib + boff));
                asm volatile(
                    "ldmatrix.sync.aligned.m8n8.x2.shared.b16 {%0,%1}, [%2];"
                    : "=r"(bl0), "=r"(bl1) : "r"(blob + boff));
                asm volatile(
                    "mma.sync.aligned.m16n8k16.row.col.f32.bf16.bf16.f32 "
                    "{%0,%1,%2,%3}, {%4,%5,%6,%7}, {%8,%9}, {%0,%1,%2,%3};"
                    : "+f"(acc[ni][0]), "+f"(acc[ni][1]),
                      "+f"(acc[ni][2]), "+f"(acc[ni][3])
                    : "r"(ah[0]), "r"(ah[1]), "r"(ah[2]), "r"(ah[3]),
                      "r"(bh0), "r"(bh1));
                asm volatile(
                    "mma.sync.aligned.m16n8k16.row.col.f32.bf16.bf16.f32 "
                    "{%0,%1,%2,%3}, {%4,%5,%6,%7}, {%8,%9}, {%0,%1,%2,%3};"
                    : "+f"(acc[ni][0]), "+f"(acc[ni][1]),
                      "+f"(acc[ni][2]), "+f"(acc[ni][3])
                    : "r"(ah[0]), "r"(ah[1]), "r"(ah[2]), "r"(ah[3]),
                      "r"(bl0), "r"(bl1));
                asm volatile(
                    "mma.sync.aligned.m16n8k16.row.col.f32.bf16.bf16.f32 "
                    "{%0,%1,%2,%3}, {%4,%5,%6,%7}, {%8,%9}, {%0,%1,%2,%3};"
                    : "+f"(acc[ni][0]), "+f"(acc[ni][1]),
                      "+f"(acc[ni][2]), "+f"(acc[ni][3])
                    : "r"(al[0]), "r"(al[1]), "r"(al[2]), "r"(al[3]),
                      "r"(bh0), "r"(bh1));
            }
        }

        const int slotBase = (g << 12) + (mblk << 6) + wm * 16 + (lane >> 2);
        const int colBase  = (nblk << 6) + wn * 32 + (lane & 3) * 2;
#pragma unroll
        for (int ni = 0; ni < 4; ni++) {
            const int col = colBase + ni * 8;
            const float b0 = 0.25f * __ldg(valb + col);
            const float b1 = 0.25f * __ldg(valb + col + 1);
            *(float2*)(g_Vtab + (size_t)slotBase * 128 + col)
                = make_float2(acc[ni][0] + b0, acc[ni][1] + b1);
            *(float2*)(g_Vtab + (size_t)(slotBase + 8) * 128 + col)
                = make_float2(acc[ni][2] + b0, acc[ni][3] + b1);
        }
    } else {
        // ============ K path: bf16 HMMA, 128 slots x 128 cols ============
        const int kIdx = bx >> 1;           // 0..511
        const int nblk = kIdx & 3;          // 0..3  (128-col tile)
        const int mblk = (kIdx >> 2) & 31;  // 0..31
        const int g    = kIdx >> 7;         // 0..3

        __nv_bfloat16* Asm = (__nv_bfloat16*)(smem_raw);
        __nv_bfloat16* Bsm = (__nv_bfloat16*)(smem_raw + 18432);

        const float* abase = emb + (size_t)((g << 12) + (mblk << 7)) * 64;
#pragma unroll
        for (int u = 0; u < 8; u++) {
            const int idx = tid + (u << 8);
            const int row = idx >> 4;
            const int c4  = idx & 15;
            float4 v = *(const float4*)(abase + row * 64 + c4 * 4);
            __nv_bfloat162 p0 = __float22bfloat162_rn(make_float2(v.x, v.y));
            __nv_bfloat162 p1 = __float22bfloat162_rn(make_float2(v.z, v.w));
            uint2 w;
            w.x = *(unsigned int*)&p0;  w.y = *(unsigned int*)&p1;
            *(uint2*)(Asm + row * 72 + c4 * 4) = w;
        }
        // B: 128 keyW rows (cols), 64 k each
        const float* bbase = keyW + (size_t)(nblk << 7) * 256 + g * 64;
#pragma unroll
        for (int u = 0; u < 8; u++) {
            const int idx = tid + (u << 8);
            const int row = idx >> 4;           // 0..127
            const int c4  = idx & 15;
            float4 v = *(const float4*)(bbase + row * 256 + c4 * 4);
            __nv_bfloat162 p0 = __float22bfloat162_rn(make_float2(v.x, v.y));
            __nv_bfloat162 p1 = __float22bfloat162_rn(make_float2(v.z, v.w));
            uint2 w;
            w.x = *(unsigned int*)&p0;  w.y = *(unsigned int*)&p1;
            *(uint2*)(Bsm + row * 72 + c4 * 4) = w;
        }
        __syncthreads();

        const int wm = warp & 3;        // 32-row strip
        const int wn = warp >> 2;       // 64-col strip (of 128)

        float acc[2][8][4];
#pragma unroll
        for (int mi = 0; mi < 2; mi++)
#pragma unroll
            for (int ni = 0; ni < 8; ni++)
#pragma unroll
                for (int r = 0; r < 4; r++) acc[mi][ni][r] = 0.f;

        const unsigned int asmb = (unsigned int)__cvta_generic_to_shared(Asm);
        const unsigned int bsmb = (unsigned int)__cvta_generic_to_shared(Bsm);
        const int arow  = lane & 15;
        const int ahalf = lane >> 4;
        const int brow  = lane & 7;
        const int bhalf = (lane >> 3) & 1;

#pragma unroll
        for (int ks = 0; ks < 4; ks++) {
            unsigned int af[2][4];
#pragma unroll
            for (int mi = 0; mi < 2; mi++) {
                unsigned int addr = asmb
                    + (unsigned int)((wm * 32 + mi * 16 + arow) * 144)
                    + ks * 32 + ahalf * 16;
                asm volatile(
                    "ldmatrix.sync.aligned.m8n8.x4.shared.b16 {%0,%1,%2,%3}, [%4];"
                    : "=r"(af[mi][0]), "=r"(af[mi][1]),
                      "=r"(af[mi][2]), "=r"(af[mi][3])
                    : "r"(addr));
            }
#pragma unroll
            for (int ni = 0; ni < 8; ni++) {
                unsigned int bf0, bf1;
                unsigned int baddr = bsmb
                    + (unsigned int)((wn * 64 + ni * 8 + brow) * 144)
                    + ks * 32 + bhalf * 16;
                asm volatile(
                    "ldmatrix.sync.aligned.m8n8.x2.shared.b16 {%0,%1}, [%2];"
                    : "=r"(bf0), "=r"(bf1) : "r"(baddr));
#pragma unroll
                for (int mi = 0; mi < 2; mi++) {
                    asm volatile(
                        "mma.sync.aligned.m16n8k16.row.col.f32.bf16.bf16.f32 "
                        "{%0,%1,%2,%3}, {%4,%5,%6,%7}, {%8,%9}, {%0,%1,%2,%3};"
                        : "+f"(acc[mi][ni][0]), "+f"(acc[mi][ni][1]),
                          "+f"(acc[mi][ni][2]), "+f"(acc[mi][ni][3])
                        : "r"(af[mi][0]), "r"(af[mi][1]),
                          "r"(af[mi][2]), "r"(af[mi][3]),
                          "r"(bf0), "r"(bf1));
                }
            }
        }

        const int slotBase = (g << 12) + (mblk << 7) + wm * 32 + (lane >> 2);
        const int colBase  = (nblk << 7) + wn * 64 + (lane & 3) * 2;
#pragma unroll
        for (int ni = 0; ni < 8; ni++) {
            const int col = colBase + ni * 8;
            const float b0 = 0.25f * __ldg(keyb + col);
            const float b1 = 0.25f * __ldg(keyb + col + 1);
#pragma unroll
            for (int mi = 0; mi < 2; mi++) {
                __nv_bfloat162 lo = __float22bfloat162_rn(
                    make_float2(acc[mi][ni][0] + b0, acc[mi][ni][1] + b1));
                __nv_bfloat162 hi = __float22bfloat162_rn(
                    make_float2(acc[mi][ni][2] + b0, acc[mi][ni][3] + b1));
                *(unsigned int*)(g_Ktab + (size_t)(slotBase + mi * 16) * 512 + col)
                    = *(unsigned int*)&lo;
                *(unsigned int*)(g_Ktab + (size_t)(slotBase + mi * 16 + 8) * 512 + col)
                    = *(unsigned int*)&hi;
            }
        }
    }
}

// ---------------------------------------------------------------------------
// Stage 2 main kernel (R16, packed f32x2 tail).
// ---------------------------------------------------------------------------
struct Tok {
    uint2      K0, K1, K2, K3;
    ulonglong2 v0, v1, v2, v3;
    float4     q;
};

__global__ void __launch_bounds__(128, 5) engram_main_kernel(
    const float* __restrict__ x,        // (B,T,4,128)
    const int*   __restrict__ ids,      // (B,T)
    const int*   __restrict__ mult,     // (2,2,3)
    const float* __restrict__ wq,       // (4,128)
    const float* __restrict__ wk,       // (4,128)
    const float* __restrict__ convw,    // (512,4)
    const float* __restrict__ convn,    // (4,128)
    float*       __restrict__ out)      // (B,T,4,128)
{
    const int stream = threadIdx.x >> 5;
    const int lane   = threadIdx.x & 31;
    const int b      = blockIdx.x >> 8;
    const int chunk  = blockIdx.x & 255;
    const int t0     = chunk * R_TOK;

    const int c = stream * 128 + lane * 4;
    const int d = lane * 4;

    const float4 wq4  = *(const float4*)(wq + c);
    const float4 wk4  = *(const float4*)(wk + c);
    const float4 wqk4 = make_float4(wq4.x * wk4.x, wq4.y * wk4.y,
                                    wq4.z * wk4.z, wq4.w * wk4.w);
    const ulonglong2 cvnP = *(const ulonglong2*)(convn + c);
    const float4 cwA = *(const float4*)(convw + (c + 0) * 4);
    const float4 cwB = *(const float4*)(convw + (c + 1) * 4);
    const float4 cwC = *(const float4*)(convw + (c + 2) * 4);
    const float4 cwD = *(const float4*)(convw + (c + 3) * 4);
    const u64 w0a = f2_pack(cwA.x, cwB.x), w0b = f2_pack(cwC.x, cwD.x);
    const u64 w1a = f2_pack(cwA.y, cwB.y), w1b = f2_pack(cwC.y, cwD.y);
    const u64 w2a = f2_pack(cwA.z, cwB.z), w2b = f2_pack(cwC.z, cwD.z);
    const u64 w3a = f2_pack(cwA.w, cwB.w), w3b = f2_pack(cwC.w, cwD.w);

    const int m00 = mult[0],  m01 = mult[1];
    const int m10 = mult[3],  m11 = mult[4];
    const int m20 = mult[6],  m21 = mult[7],  m22 = mult[8];
    const int m30 = mult[9],  m31 = mult[10], m32 = mult[11];

    const float inv128     = 0.0078125f;
    const float eps        = 1.1920929e-7f;
    const float invsqrt128 = 0.08838834764831845f;

    const int    idBase = b * Tq;
    const float* xBase  = x   + (size_t)idBase * CHq + c;
    float*       oBase  = out + (size_t)idBase * CHq + c;

    u64 h1a = 0, h1b = 0, h2a = 0, h2b = 0, h3a = 0, h3b = 0;

    auto gather = [&](Tok& T, int ia, int ib, int ic, int t) {
        const int h0i = (((ib * m00) ^ (ic * m01)) & 4095);
        const int h1i = (((ib * m10) ^ (ic * m11)) & 4095) + 4096;
        const int h2i = (((ia * m20) ^ (ib * m21) ^ (ic * m22)) & 4095) + 8192;
        const int h3i = (((ia * m30) ^ (ib * m31) ^ (ic * m32)) & 4095) + 12288;
        T.K0 = __ldg((const uint2*)(g_Ktab + (size_t)h0i * 512 + c));
        T.K1 = __ldg((const uint2*)(g_Ktab + (size_t)h1i * 512 + c));
        T.K2 = __ldg((const uint2*)(g_Ktab + (size_t)h2i * 512 + c));
        T.K3 = __ldg((const uint2*)(g_Ktab + (size_t)h3i * 512 + c));
        T.v0 = __ldg((const ulonglong2*)(g_Vtab + (size_t)h0i * 128 + d));
        T.v1 = __ldg((const ulonglong2*)(g_Vtab + (size_t)h1i * 128 + d));
        T.v2 = __ldg((const ulonglong2*)(g_Vtab + (size_t)h2i * 128 + d));
        T.v3 = __ldg((const ulonglong2*)(g_Vtab + (size_t)h3i * 128 + d));
        T.q  = *(const float4*)(xBase + (size_t)t * CHq);
    };

    auto compute = [&](const Tok& T, int t, bool store) {
        float2 k0a = __bfloat1622float2(*(const __nv_bfloat162*)&T.K0.x);
        float2 k0b = __bfloat1622float2(*(const __nv_bfloat162*)&T.K0.y);
        float2 k1a = __bfloat1622float2(*(const __nv_bfloat162*)&T.K1.x);
        float2 k1b = __bfloat1622float2(*(const __nv_bfloat162*)&T.K1.y);
        float2 k2a = __bfloat1622float2(*(const __nv_bfloat162*)&T.K2.x);
        float2 k2b = __bfloat1622float2(*(const __nv_bfloat162*)&T.K2.y);
        float2 k3a = __bfloat1622float2(*(const __nv_bfloat162*)&T.K3.x);
        float2 k3b = __bfloat1622float2(*(const __nv_bfloat162*)&T.K3.y);
        float4 kr;
        kr.x = (k0a.x + k1a.x) + (k2a.x + k3a.x);
        kr.y = (k0a.y + k1a.y) + (k2a.y + k3a.y);
        kr.z = (k0b.x + k1b.x) + (k2b.x + k3b.x);
        kr.w = (k0b.y + k1b.y) + (k2b.y + k3b.y);

        const u64 vbA = f2_add(f2_add(T.v0.x, T.v1.x), f2_add(T.v2.x, T.v3.x));
        const u64 vbB = f2_add(f2_add(T.v0.y, T.v1.y), f2_add(T.v2.y, T.v3.y));

        u64 t3 = f2_mul(vbA, vbA);
        t3 = f2_fma(vbB, vbB, t3);
        float2 t3u = f2_unpack(t3);
        float p3 = t3u.x + t3u.y;

        float p0 = T.q.x * T.q.x + T.q.y * T.q.y + T.q.z * T.q.z + T.q.w * T.q.w;
        float p1 = kr.x * kr.x + kr.y * kr.y + kr.z * kr.z + kr.w * kr.w;
        float p2 = T.q.x * kr.x * wqk4.x + T.q.y * kr.y * wqk4.y
                 + T.q.z * kr.z * wqk4.z + T.q.w * kr.w * wqk4.w;

        const bool lo = (lane < 16);
        float ea = __shfl_xor_sync(0xffffffffu, p0, 16);
        float eb = __shfl_xor_sync(0xffffffffu, p2, 16);
        float aa = lo ? (p0 + ea) : (p2 + eb);
        float ec = __shfl_xor_sync(0xffffffffu, p1, 16);
        float ed = __shfl_xor_sync(0xffffffffu, p3, 16);
        float bb = lo ? (p1 + ec) : (p3 + ed);
#pragma unroll
        for (int off = 8; off; off >>= 1) {
            aa += __shfl_xor_sync(0xffffffffu, aa, off);
            bb += __shfl_xor_sync(0xffffffffu, bb, off);
        }
        const float a2 = __shfl_xor_sync(0xffffffffu, aa, 16);
        const float b2 = __shfl_xor_sync(0xffffffffu, bb, 16);
        const float sq  = lo ? aa : a2;
        const float sk  = lo ? bb : b2;
        const float sqk = lo ? a2 : aa;
        const float svb = lo ? b2 : bb;

        const float rsq   = rsqrtf(sq * inv128 + eps);
        const float rsk   = rsqrtf(sk * inv128 + eps);
        const float score = sqk * rsq * rsk * invsqrt128;
        const float gate  = __fdividef(1.f, 1.f + __expf(-score));
        const float rr    = rsqrtf(gate * gate * svb * inv128 + eps) * gate;

        const u64 rr2 = f2_pack(rr, rr);
        const u64 xnA = f2_mul(f2_mul(vbA, rr2), cvnP.x);
        const u64 xnB = f2_mul(f2_mul(vbB, rr2), cvnP.y);

        if (store) {
            u64 yA = f2_mul(w3a, xnA);
            yA = f2_fma(w2a, h1a, yA);
            yA = f2_fma(w1a, h2a, yA);
            yA = f2_fma(w0a, h3a, yA);
            u64 yB = f2_mul(w3b, xnB);
            yB = f2_fma(w2b, h1b, yB);
            yB = f2_fma(w1b, h2b, yB);
            yB = f2_fma(w0b, h3b, yB);

            float2 ya = f2_unpack(yA);
            float2 yb = f2_unpack(yB);
            ya.x = __fdividef(ya.x, 1.f + __expf(-ya.x));
            ya.y = __fdividef(ya.y, 1.f + __expf(-ya.y));
            yb.x = __fdividef(yb.x, 1.f + __expf(-yb.x));
            yb.y = __fdividef(yb.y, 1.f + __expf(-yb.y));

            const u64 gate2 = f2_pack(gate, gate);
            ulonglong2 o;
            o.x = f2_fma(vbA, gate2, f2_pack(ya.x, ya.y));
            o.y = f2_fma(vbB, gate2, f2_pack(yb.x, yb.y));
            *(ulonglong2*)(oBase + (size_t)t * CHq) = o;
        }
        h3a = h2a; h3b = h2b;
        h2a = h1a; h2b = h1b;
        h1a = xnA; h1b = xnB;
    };

    int ia = (t0 - 5 >= 0) ? __ldg(ids + idBase + t0 - 5) : 0;
    int ib = (t0 - 4 >= 0) ? __ldg(ids + idBase + t0 - 4) : 0;

#pragma unroll
    for (int tt = -3; tt < 0; tt++) {
        const int t  = t0 + tt;
        const int ic = (t >= 0) ? __ldg(ids + idBase + t) : 0;
        if (t >= 0) {
            Tok P;
            gather(P, ia, ib, ic, t);
            compute(P, t, false);
        }
        ia = ib; ib = ic;
    }

    int ic = __ldg(ids + idBase + t0);
    Tok cur;
    gather(cur, ia, ib, ic, t0);

    for (int tt = 0; tt < R_TOK; tt++) {
        const int t = t0 + tt;
        Tok nxt;
        int in_ = ic;
        if (tt + 1 < R_TOK) {
            in_ = __ldg(ids + idBase + t + 1);
            gather(nxt, ib, ic, in_, t + 1);
        }
        compute(cur, t, true);
        ia = ib; ib = ic; ic = in_;
        cur = nxt;
    }
}

// ---------------------------------------------------------------------------
extern "C" void kernel_launch(void* const* d_in, const int* in_sizes, int n_in,
                              void* d_out, int out_size)
{
    const float* x          = (const float*)d_in[0];
    const int*   input_ids  = (const int*)  d_in[1];
    const int*   multipliers= (const int*)  d_in[2];
    const float* embedding  = (const float*)d_in[3];
    const float* val_W      = (const float*)d_in[4];
    const float* val_b      = (const float*)d_in[5];
    const float* key_W      = (const float*)d_in[6];
    const float* key_b      = (const float*)d_in[7];
    const float* normq_w    = (const float*)d_in[8];
    const float* normk_w    = (const float*)d_in[9];
    const float* conv_w     = (const float*)d_in[10];
    const float* convnorm_w = (const float*)d_in[11];
    float* out = (float*)d_out;

    precompute_kernel<<<1024, 256>>>(embedding, val_W, val_b, key_W, key_b);

    engram_main_kernel<<<Bq * CHUNKS, 128>>>(
        x, input_ids, multipliers,
        normq_w, normk_w, conv_w, convnorm_w, out);
}